// round 1
// baseline (speedup 1.0000x reference)
#include <cuda_runtime.h>
#include <math.h>

// Fused DTCWT scattering layer:
//   horizontal filt (h0:5-tap lo, h1:7-tap hi, symmetric pad)
//   vertical filt  (ll, lh, hl, hh)
//   q2c (downsample 2x2 -> complex pairs), magnitudes, LL 2x2 mean-pool
// x: (32,3,512,512) f32  ->  out: (32,21,256,256) f32
// out channel layout: ch = s*3 + c, s=0:ll, s=1..6: |d15|,|d45|,|d75|,|d105|,|d135|,|d165|

#define TILE_OX 64                 // output cols per tile
#define TILE_OY 16                 // output rows per tile
#define RW (2*TILE_OX)             // 128 subband-region cols
#define RH (2*TILE_OY)             // 32 subband-region rows
#define HALO 3
#define XS_H (RH + 2*HALO)         // 38
#define XS_W (RW + 2*HALO)         // 134
#define XS_WP 136                  // padded pitch (8B align)
#define NTHREADS 256
#define SMEM_FLOATS (XS_H*XS_WP + 2*XS_H*RW)   // 5168 + 9728 = 14896
#define SMEM_BYTES (SMEM_FLOATS*4)             // 59584

__global__ __launch_bounds__(NTHREADS) void scat_kernel(
    const float* __restrict__ x,
    const float* __restrict__ h0,
    const float* __restrict__ h1,
    float* __restrict__ out)
{
    extern __shared__ float sm[];
    float* xs   = sm;                       // [XS_H][XS_WP]
    float* lo_s = sm + XS_H*XS_WP;          // [XS_H][RW]
    float* hi_s = lo_s + XS_H*RW;           // [XS_H][RW]
    __shared__ float f0[5], f1[7];

    const int tid = threadIdx.x;
    if (tid < 5) f0[tid] = h0[tid];
    if (tid < 7) f1[tid] = h1[tid];

    const int img = blockIdx.z;             // b*3 + c, 0..95
    const int gx0 = blockIdx.x * RW;        // input-space col base of region
    const int gy0 = blockIdx.y * RH;        // input-space row base of region
    const float* xin = x + (size_t)img * (512*512);

    // ---- Phase 1: stage x tile (with symmetric-padded halo) into SMEM ----
    for (int i = tid; i < XS_H*XS_W; i += NTHREADS) {
        int r = i / XS_W, c = i - r*XS_W;
        int gy = gy0 - HALO + r;
        int gx = gx0 - HALO + c;
        gy = gy < 0 ? -gy-1 : (gy > 511 ? 1023-gy : gy);
        gx = gx < 0 ? -gx-1 : (gx > 511 ? 1023-gx : gx);
        xs[r*XS_WP + c] = __ldg(&xin[gy*512 + gx]);
    }
    __syncthreads();

    // ---- Phase 2: horizontal filters -> lo (5-tap), hi (7-tap) ----
    for (int i = tid; i < XS_H*RW; i += NTHREADS) {
        int r = i / RW, c = i - r*RW;
        const float* p = &xs[r*XS_WP + c];  // p[j] = xs col (c+j); center = c+HALO
        float lo = p[1]*f0[0] + p[2]*f0[1] + p[3]*f0[2] + p[4]*f0[3] + p[5]*f0[4];
        float hi = p[0]*f1[0] + p[1]*f1[1] + p[2]*f1[2] + p[3]*f1[3]
                 + p[4]*f1[4] + p[5]*f1[5] + p[6]*f1[6];
        lo_s[r*RW + c] = lo;
        hi_s[r*RW + c] = hi;
    }
    __syncthreads();

    // ---- Phase 3: vertical filters + q2c + magnitudes + LL pool + store ----
    const int tx  = tid & (TILE_OX-1);      // 0..63
    const int ty0 = tid / TILE_OX;          // 0..3
    const int b_  = img / 3;
    const int ch_ = img % 3;
    const int ox_g = (gx0 >> 1) + tx;
    const float inv_s2 = 0.70710678118654752f;

    auto mag = [](float re, float im) {
        return sqrtf(re*re + im*im + 1e-4f) - 0.01f;
    };

    for (int oy = ty0; oy < TILE_OY; oy += NTHREADS/TILE_OX) {
        float LL[2][2], LH[2][2], HL[2][2], HH[2][2];
        #pragma unroll
        for (int dr = 0; dr < 2; dr++) {
            const int rr = 2*oy + dr + HALO;     // smem row of this quad row
            float2 v[7], w[7];
            #pragma unroll
            for (int t = 0; t < 7; t++) {
                v[t] = *(const float2*)&lo_s[(rr-3+t)*RW + 2*tx];
                w[t] = *(const float2*)&hi_s[(rr-3+t)*RW + 2*tx];
            }
            // 5-tap (h0) uses taps 1..5; 7-tap (h1) uses taps 0..6
            LL[dr][0] = v[1].x*f0[0]+v[2].x*f0[1]+v[3].x*f0[2]+v[4].x*f0[3]+v[5].x*f0[4];
            LL[dr][1] = v[1].y*f0[0]+v[2].y*f0[1]+v[3].y*f0[2]+v[4].y*f0[3]+v[5].y*f0[4];
            HL[dr][0] = w[1].x*f0[0]+w[2].x*f0[1]+w[3].x*f0[2]+w[4].x*f0[3]+w[5].x*f0[4];
            HL[dr][1] = w[1].y*f0[0]+w[2].y*f0[1]+w[3].y*f0[2]+w[4].y*f0[3]+w[5].y*f0[4];
            LH[dr][0] = v[0].x*f1[0]+v[1].x*f1[1]+v[2].x*f1[2]+v[3].x*f1[3]
                      + v[4].x*f1[4]+v[5].x*f1[5]+v[6].x*f1[6];
            LH[dr][1] = v[0].y*f1[0]+v[1].y*f1[1]+v[2].y*f1[2]+v[3].y*f1[3]
                      + v[4].y*f1[4]+v[5].y*f1[5]+v[6].y*f1[6];
            HH[dr][0] = w[0].x*f1[0]+w[1].x*f1[1]+w[2].x*f1[2]+w[3].x*f1[3]
                      + w[4].x*f1[4]+w[5].x*f1[5]+w[6].x*f1[6];
            HH[dr][1] = w[0].y*f1[0]+w[1].y*f1[1]+w[2].y*f1[2]+w[3].y*f1[3]
                      + w[4].y*f1[4]+w[5].y*f1[5]+w[6].y*f1[6];
        }

        float llp = 0.25f*(LL[0][0]+LL[0][1]+LL[1][0]+LL[1][1]);

        // quad (a,b,c,d) = S[0][0], S[0][1], S[1][0], S[1][1], scaled by 1/sqrt2
        // pair1 = (a-d, b+c), pair2 = (a+d, b-c)
        float m15  = mag((LH[0][0]-LH[1][1])*inv_s2, (LH[0][1]+LH[1][0])*inv_s2);
        float m165 = mag((LH[0][0]+LH[1][1])*inv_s2, (LH[0][1]-LH[1][0])*inv_s2);
        float m45  = mag((HH[0][0]-HH[1][1])*inv_s2, (HH[0][1]+HH[1][0])*inv_s2);
        float m135 = mag((HH[0][0]+HH[1][1])*inv_s2, (HH[0][1]-HH[1][0])*inv_s2);
        float m75  = mag((HL[0][0]-HL[1][1])*inv_s2, (HL[0][1]+HL[1][0])*inv_s2);
        float m105 = mag((HL[0][0]+HL[1][1])*inv_s2, (HL[0][1]-HL[1][0])*inv_s2);

        const int oy_g = (gy0 >> 1) + oy;
        size_t base = (((size_t)b_*21 + ch_)*256 + oy_g)*256 + ox_g;
        const size_t cs = (size_t)3*256*256;   // stride between subband groups
        out[base       ] = llp;
        out[base + 1*cs] = m15;
        out[base + 2*cs] = m45;
        out[base + 3*cs] = m75;
        out[base + 4*cs] = m105;
        out[base + 5*cs] = m135;
        out[base + 6*cs] = m165;
    }
}

extern "C" void kernel_launch(void* const* d_in, const int* in_sizes, int n_in,
                              void* d_out, int out_size) {
    const float* x  = (const float*)d_in[0];
    const float* h0 = (const float*)d_in[1];
    const float* h1 = (const float*)d_in[2];
    float* out = (float*)d_out;

    cudaFuncSetAttribute(scat_kernel,
                         cudaFuncAttributeMaxDynamicSharedMemorySize, SMEM_BYTES);

    dim3 grid(256/TILE_OX, 256/TILE_OY, 96);   // (4, 16, 96)
    scat_kernel<<<grid, NTHREADS, SMEM_BYTES>>>(x, h0, h1, out);
}

// round 2
// speedup vs baseline: 1.9313x; 1.9313x over previous
#include <cuda_runtime.h>
#include <math.h>

// Fused DTCWT scattering layer, round 2:
//  - horizontal filters computed straight from global (L1-cached overlap), no x staging
//  - lo/hi interleaved as float4 quads in SMEM -> LDS.128 in vertical phase
//  - vertical filt + q2c + magnitudes + LL 2x2 pool, 7 coalesced stores
// x: (32,3,512,512) f32 -> out: (32,21,256,256) f32

#define TILE_OX 64                 // output cols per tile
#define TILE_OY 16                 // output rows per tile
#define RW (2*TILE_OX)             // 128 region cols
#define RH (2*TILE_OY)             // 32 region rows
#define HALO 3
#define QH (RH + 2*HALO)           // 38 quad rows
#define QW TILE_OX                 // 64 pair-columns
#define NTHREADS 256
#define SMEM_BYTES (QH*QW*16)      // 38*64*16 = 38912

__device__ __forceinline__ int refl(int i) {
    i = (i < 0) ? (-i - 1) : i;
    return (i > 511) ? (1023 - i) : i;
}

__global__ __launch_bounds__(NTHREADS, 5) void scat_kernel(
    const float* __restrict__ x,
    const float* __restrict__ h0,
    const float* __restrict__ h1,
    float* __restrict__ out)
{
    extern __shared__ float4 q[];           // [QH][QW]: (lo0, lo1, hi0, hi1)

    const int tid = threadIdx.x;
    const int img = blockIdx.z;             // b*3 + c
    const int gx0 = blockIdx.x * RW;
    const int gy0 = blockIdx.y * RH;
    const float* __restrict__ xin = x + (size_t)img * (512*512);

    // filter coeffs into registers (broadcast, L1-hit)
    const float f00 = __ldg(&h0[0]), f01 = __ldg(&h0[1]), f02 = __ldg(&h0[2]),
                f03 = __ldg(&h0[3]), f04 = __ldg(&h0[4]);
    const float f10 = __ldg(&h1[0]), f11 = __ldg(&h1[1]), f12 = __ldg(&h1[2]),
                f13 = __ldg(&h1[3]), f14 = __ldg(&h1[4]), f15 = __ldg(&h1[5]),
                f16 = __ldg(&h1[6]);

    // ---- Phase A: horizontal filters straight from gmem -> interleaved quads ----
    for (int i = tid; i < QH*QW; i += NTHREADS) {
        const int r = i >> 6;               // 0..37
        const int c = i & 63;               // pair-column
        const int gy = refl(gy0 + r - HALO);
        const float* __restrict__ xr = xin + gy*512;
        const int cb = gx0 + 2*c - 3;
        float w0 = __ldg(&xr[refl(cb+0)]);
        float w1 = __ldg(&xr[refl(cb+1)]);
        float w2 = __ldg(&xr[refl(cb+2)]);
        float w3 = __ldg(&xr[refl(cb+3)]);
        float w4 = __ldg(&xr[refl(cb+4)]);
        float w5 = __ldg(&xr[refl(cb+5)]);
        float w6 = __ldg(&xr[refl(cb+6)]);
        float w7 = __ldg(&xr[refl(cb+7)]);

        float4 v;
        v.x = w1*f00 + w2*f01 + w3*f02 + w4*f03 + w5*f04;                 // lo @ 2c
        v.y = w2*f00 + w3*f01 + w4*f02 + w5*f03 + w6*f04;                 // lo @ 2c+1
        v.z = w0*f10 + w1*f11 + w2*f12 + w3*f13 + w4*f14 + w5*f15 + w6*f16; // hi @ 2c
        v.w = w1*f10 + w2*f11 + w3*f12 + w4*f13 + w5*f14 + w6*f15 + w7*f16; // hi @ 2c+1
        q[r*QW + c] = v;
    }
    __syncthreads();

    // ---- Phase B: vertical filters + q2c + magnitudes + pool + store ----
    const int tx  = tid & (TILE_OX-1);      // 0..63
    const int ty0 = tid >> 6;               // 0..3
    const int b_  = img / 3;
    const int ch_ = img % 3;
    const int ox_g = (gx0 >> 1) + tx;
    const float inv_s2 = 0.70710678118654752f;

    for (int oy = ty0; oy < TILE_OY; oy += NTHREADS/TILE_OX) {
        // accumulators: [sub][dr][col]; dr0 window rows j=0..6, dr1 rows j=1..7
        float LL0x=0.f,LL0y=0.f,LL1x=0.f,LL1y=0.f;
        float LH0x=0.f,LH0y=0.f,LH1x=0.f,LH1y=0.f;
        float HL0x=0.f,HL0y=0.f,HL1x=0.f,HL1y=0.f;
        float HH0x=0.f,HH0y=0.f,HH1x=0.f,HH1y=0.f;

        const float4* __restrict__ qc = q + 2*oy*QW + tx;
        #pragma unroll
        for (int j = 0; j < 8; j++) {
            const float4 v = qc[j*QW];      // (lo0, lo1, hi0, hi1) at quad-row 2oy+j
            if (j < 7) {                    // dr=0, h1 tap j
                const float c1 = (j==0?f10:j==1?f11:j==2?f12:j==3?f13:j==4?f14:j==5?f15:f16);
                LH0x += c1*v.x; LH0y += c1*v.y; HH0x += c1*v.z; HH0y += c1*v.w;
            }
            if (j >= 1 && j <= 5) {         // dr=0, h0 tap j-1
                const float c0 = (j==1?f00:j==2?f01:j==3?f02:j==4?f03:f04);
                LL0x += c0*v.x; LL0y += c0*v.y; HL0x += c0*v.z; HL0y += c0*v.w;
            }
            if (j >= 1) {                   // dr=1, h1 tap j-1
                const float c1 = (j==1?f10:j==2?f11:j==3?f12:j==4?f13:j==5?f14:j==6?f15:f16);
                LH1x += c1*v.x; LH1y += c1*v.y; HH1x += c1*v.z; HH1y += c1*v.w;
            }
            if (j >= 2 && j <= 6) {         // dr=1, h0 tap j-2
                const float c0 = (j==2?f00:j==3?f01:j==4?f02:j==5?f03:f04);
                LL1x += c0*v.x; LL1y += c0*v.y; HL1x += c0*v.z; HL1y += c0*v.w;
            }
        }

        const float llp = 0.25f*(LL0x + LL0y + LL1x + LL1y);

        // quad (a,b,c,d) = (S[0][0], S[0][1], S[1][0], S[1][1]) * 1/sqrt2
        // band1 = (a-d, b+c), band2 = (a+d, b-c); mag = sqrt(re^2+im^2+1e-4) - 0.01
        #define MAG(re, im) (sqrtf((re)*(re) + (im)*(im) + 1e-4f) - 0.01f)
        const float m15  = MAG((LH0x-LH1y)*inv_s2, (LH0y+LH1x)*inv_s2);
        const float m165 = MAG((LH0x+LH1y)*inv_s2, (LH0y-LH1x)*inv_s2);
        const float m45  = MAG((HH0x-HH1y)*inv_s2, (HH0y+HH1x)*inv_s2);
        const float m135 = MAG((HH0x+HH1y)*inv_s2, (HH0y-HH1x)*inv_s2);
        const float m75  = MAG((HL0x-HL1y)*inv_s2, (HL0y+HL1x)*inv_s2);
        const float m105 = MAG((HL0x+HL1y)*inv_s2, (HL0y-HL1x)*inv_s2);
        #undef MAG

        const int oy_g = (gy0 >> 1) + oy;
        size_t base = (((size_t)b_*21 + ch_)*256 + oy_g)*256 + ox_g;
        const size_t cs = (size_t)3*256*256;
        out[base       ] = llp;
        out[base + 1*cs] = m15;
        out[base + 2*cs] = m45;
        out[base + 3*cs] = m75;
        out[base + 4*cs] = m105;
        out[base + 5*cs] = m135;
        out[base + 6*cs] = m165;
    }
}

extern "C" void kernel_launch(void* const* d_in, const int* in_sizes, int n_in,
                              void* d_out, int out_size) {
    const float* x  = (const float*)d_in[0];
    const float* h0 = (const float*)d_in[1];
    const float* h1 = (const float*)d_in[2];
    float* out = (float*)d_out;

    cudaFuncSetAttribute(scat_kernel,
                         cudaFuncAttributeMaxDynamicSharedMemorySize, SMEM_BYTES);

    dim3 grid(256/TILE_OX, 256/TILE_OY, 96);   // (4, 16, 96)
    scat_kernel<<<grid, NTHREADS, SMEM_BYTES>>>(x, h0, h1, out);
}

// round 4
// speedup vs baseline: 2.1395x; 1.1078x over previous
#include <cuda_runtime.h>
#include <math.h>

// Fused DTCWT scattering layer, round 3: register-resident column sliding window.
//  - no shared memory, no __syncthreads
//  - each thread owns one pair-column (2 input cols), CTA covers full 512-wide row
//  - 8-row register ring of horizontal-filter quads (lo0,lo1,hi0,hi1)
//  - filter taps hardcoded as immediates (fixed constants in the problem), FFMA-imm rate
// x: (32,3,512,512) f32 -> out: (32,21,256,256) f32

#define TILE_OY 16
#define NTHREADS 256

// h0 (symmetric): [-0.05, 0.25, 0.6, 0.25, -0.05]
#define G0 (-0.05f)
#define G1 (0.25f)
#define G2 (0.6f)
#define G3 (0.25f)
#define G4 (-0.05f)
// h1 (symmetric): [-0.0107143, 0.0535714, 0.2607143, -0.6071429, 0.2607143, 0.0535714, -0.0107143]
#define H0 (-0.0107143f)
#define H1 (0.0535714f)
#define H2 (0.2607143f)
#define H3 (-0.6071429f)
#define H4 (0.2607143f)
#define H5 (0.0535714f)
#define H6 (-0.0107143f)

__device__ __forceinline__ int refl(int i) {
    i = (i < 0) ? (-i - 1) : i;
    return (i > 511) ? (1023 - i) : i;
}

__device__ __forceinline__ float sqrt_approx(float v) {
    float r;
    asm("sqrt.approx.f32 %0, %1;" : "=f"(r) : "f"(v));
    return r;
}

// mag for q2c band: inputs are raw (un-scaled) re/im; band value = sqrt((re^2+im^2)/2 + 1e-4) - 0.01
__device__ __forceinline__ float bandmag(float re, float im) {
    return sqrt_approx(0.5f * fmaf(re, re, fmaf(im, im, 2e-4f))) - 0.01f;
}

// horizontal filters for one input row at pair-column c: returns (lo@2c, lo@2c+1, hi@2c, hi@2c+1)
__device__ __forceinline__ float4 hfilt_row(const float* __restrict__ xr, int c, bool edge) {
    float w0, w1, w2, w3, w4, w5, w6, w7;   // cols 2c-3 .. 2c+4
    if (!edge) {
        const float2 pa = __ldg((const float2*)(xr + 2*c - 4));
        const float2 pb = __ldg((const float2*)(xr + 2*c - 2));
        const float2 pc = __ldg((const float2*)(xr + 2*c    ));
        const float2 pd = __ldg((const float2*)(xr + 2*c + 2));
        const float2 pe = __ldg((const float2*)(xr + 2*c + 4));
        w0 = pa.y; w1 = pb.x; w2 = pb.y; w3 = pc.x;
        w4 = pc.y; w5 = pd.x; w6 = pd.y; w7 = pe.x;
    } else {
        w0 = __ldg(xr + refl(2*c - 3));
        w1 = __ldg(xr + refl(2*c - 2));
        w2 = __ldg(xr + refl(2*c - 1));
        w3 = __ldg(xr + refl(2*c    ));
        w4 = __ldg(xr + refl(2*c + 1));
        w5 = __ldg(xr + refl(2*c + 2));
        w6 = __ldg(xr + refl(2*c + 3));
        w7 = __ldg(xr + refl(2*c + 4));
    }
    float4 v;
    v.x = G0*w1 + G1*w2 + G2*w3 + G3*w4 + G4*w5;
    v.y = G0*w2 + G1*w3 + G2*w4 + G3*w5 + G4*w6;
    v.z = H0*w0 + H1*w1 + H2*w2 + H3*w3 + H4*w4 + H5*w5 + H6*w6;
    v.w = H0*w1 + H1*w2 + H2*w3 + H3*w3*0.0f + H3*w4 + H4*w5 + H5*w6 + H6*w7; // placeholder fixed below
    v.w = H0*w1 + H1*w2 + H2*w3 + H3*w4 + H4*w5 + H5*w6 + H6*w7;
    return v;
}

__global__ __launch_bounds__(NTHREADS, 4) void scat_kernel(
    const float* __restrict__ x,
    float* __restrict__ out)
{
    const int c   = threadIdx.x;            // pair-column 0..255
    const int img = blockIdx.z;             // b*3 + ch
    const int OY0 = blockIdx.y * TILE_OY;
    const float* __restrict__ xin = x + (size_t)img * (512*512);
    const bool edge = (c < 2) || (c > 253);

    const int b_  = img / 3;
    const int ch_ = img % 3;
    size_t obase = (((size_t)b_*21 + ch_)*256 + OY0)*256 + c;
    const size_t cs = (size_t)3*256*256;

    const int R = 2*OY0 - 3;                // first input row of window

    float4 ring[8];
    #pragma unroll
    for (int j = 0; j < 6; j++) {
        const int gy = refl(R + j);
        ring[j] = hfilt_row(xin + (size_t)gy*512, c, edge);
    }

    #pragma unroll 1
    for (int k4 = 0; k4 < TILE_OY/4; ++k4) {
        #pragma unroll
        for (int u = 0; u < 4; ++u) {
            const int oy = k4*4 + u;
            // load the two new rows completing window [2oy .. 2oy+7]
            {
                const int gy0r = refl(R + 6 + 2*oy);
                ring[(6 + 2*u) & 7] = hfilt_row(xin + (size_t)gy0r*512, c, edge);
                const int gy1r = refl(R + 7 + 2*oy);
                ring[(7 + 2*u) & 7] = hfilt_row(xin + (size_t)gy1r*512, c, edge);
            }

            const float4 q0 = ring[(2*u + 0) & 7];
            const float4 q1 = ring[(2*u + 1) & 7];
            const float4 q2 = ring[(2*u + 2) & 7];
            const float4 q3 = ring[(2*u + 3) & 7];
            const float4 q4 = ring[(2*u + 4) & 7];
            const float4 q5 = ring[(2*u + 5) & 7];
            const float4 q6 = ring[(2*u + 6) & 7];
            const float4 q7 = ring[(2*u + 7) & 7];

            // ---- lo plane (.x,.y): LL (pooled), LH -> m15, m165 ----
            float LH0x = H0*q0.x + H1*q1.x + H2*q2.x + H3*q3.x + H4*q4.x + H5*q5.x + H6*q6.x;
            float LH0y = H0*q0.y + H1*q1.y + H2*q2.y + H3*q3.y + H4*q4.y + H5*q5.y + H6*q6.y;
            float LH1x = H0*q1.x + H1*q2.x + H2*q3.x + H3*q4.x + H4*q5.x + H5*q6.x + H6*q7.x;
            float LH1y = H0*q1.y + H1*q2.y + H2*q3.y + H3*q4.y + H4*q5.y + H5*q6.y + H6*q7.y;
            float LL0x = G0*q1.x + G1*q2.x + G2*q3.x + G3*q4.x + G4*q5.x;
            float LL0y = G0*q1.y + G1*q2.y + G2*q3.y + G3*q4.y + G4*q5.y;
            float LL1x = G0*q2.x + G1*q3.x + G2*q4.x + G3*q5.x + G4*q6.x;
            float LL1y = G0*q2.y + G1*q3.y + G2*q4.y + G3*q5.y + G4*q6.y;

            const float llp  = 0.25f*(LL0x + LL0y + LL1x + LL1y);
            const float m15  = bandmag(LH0x - LH1y, LH0y + LH1x);
            const float m165 = bandmag(LH0x + LH1y, LH0y - LH1x);

            // ---- hi plane (.z,.w): HL -> m75, m105 ; HH -> m45, m135 ----
            float HH0x = H0*q0.z + H1*q1.z + H2*q2.z + H3*q3.z + H4*q4.z + H5*q5.z + H6*q6.z;
            float HH0y = H0*q0.w + H1*q1.w + H2*q2.w + H3*q3.w + H4*q4.w + H5*q5.w + H6*q6.w;
            float HH1x = H0*q1.z + H1*q2.z + H2*q3.z + H3*q4.z + H4*q5.z + H5*q6.z + H6*q7.z;
            float HH1y = H0*q1.w + H1*q2.w + H2*q3.w + H3*q4.w + H4*q5.w + H5*q6.w + H6*q7.w;
            float HL0x = G0*q1.z + G1*q2.z + G2*q3.z + G3*q4.z + G4*q5.z;
            float HL0y = G0*q1.w + G1*q2.w + G2*q3.w + G3*q4.w + G4*q5.w;
            float HL1x = G0*q2.z + G1*q3.z + G2*q4.z + G3*q5.z + G4*q6.z;
            float HL1y = G0*q2.w + G1*q3.w + G2*q4.w + G3*q5.w + G4*q6.w;

            const float m45  = bandmag(HH0x - HH1y, HH0y + HH1x);
            const float m135 = bandmag(HH0x + HH1y, HH0y - HH1x);
            const float m75  = bandmag(HL0x - HL1y, HL0y + HL1x);
            const float m105 = bandmag(HL0x + HL1y, HL0y - HL1x);

            float* o = out + obase + (size_t)oy*256;
            o[0]    = llp;
            o[1*cs] = m15;
            o[2*cs] = m45;
            o[3*cs] = m75;
            o[4*cs] = m105;
            o[5*cs] = m135;
            o[6*cs] = m165;
        }
    }
}

extern "C" void kernel_launch(void* const* d_in, const int* in_sizes, int n_in,
                              void* d_out, int out_size) {
    const float* x = (const float*)d_in[0];
    float* out = (float*)d_out;

    dim3 grid(1, 256/TILE_OY, 96);          // (1, 16, 96)
    scat_kernel<<<grid, NTHREADS>>>(x, out);
}

// round 6
// speedup vs baseline: 2.5299x; 1.1825x over previous
#include <cuda_runtime.h>
#include <math.h>

// Fused DTCWT scattering layer, round 4: cp.async row pipeline + register quad ring.
//  - 8-slot smem ring of raw input rows, staged with cp.async.cg (1 op/thread/iter)
//  - horizontal filters from smem (LDS), taps as immediates (FFMA-imm)
//  - vertical filt + q2c + magnitudes + LL pool in registers, 7 coalesced stores
// x: (32,3,512,512) f32 -> out: (32,21,256,256) f32

#define TILE_OY 16
#define NTHREADS 256
#define ROWSTRIDE 520              // floats per smem row slot (16B-aligned stride)
#define NSLOT 8

// h0: [-0.05, 0.25, 0.6, 0.25, -0.05]
#define G0 (-0.05f)
#define G1 (0.25f)
#define G2 (0.6f)
#define G3 (0.25f)
#define G4 (-0.05f)
// h1: [-0.0107143, 0.0535714, 0.2607143, -0.6071429, 0.2607143, 0.0535714, -0.0107143]
#define H0 (-0.0107143f)
#define H1 (0.0535714f)
#define H2 (0.2607143f)
#define H3 (-0.6071429f)
#define H4 (0.2607143f)
#define H5 (0.0535714f)
#define H6 (-0.0107143f)

__device__ __forceinline__ int refl(int i) {
    i = (i < 0) ? (-i - 1) : i;
    return (i > 511) ? (1023 - i) : i;
}

__device__ __forceinline__ float sqrt_approx(float v) {
    float r;
    asm("sqrt.approx.f32 %0, %1;" : "=f"(r) : "f"(v));
    return r;
}

// band value = sqrt((re^2+im^2)/2 + 1e-4) - 0.01   (1/sqrt2 folded into the square)
__device__ __forceinline__ float bandmag(float re, float im) {
    return sqrt_approx(0.5f * fmaf(re, re, fmaf(im, im, 2e-4f))) - 0.01f;
}

// stage rows grow0, grow0+1 into slots slot0, slot0+1 (one 16B cp.async per thread)
__device__ __forceinline__ void stage2(const float* __restrict__ xin, float* srow,
                                       int c, int slot0, int grow0) {
    const int rl    = c >> 7;              // 0/1: which of the two rows
    const int chunk = c & 127;             // 16B chunk within the row
    const int gy    = refl(grow0 + rl);
    const float* src = xin + (size_t)gy * 512 + chunk * 4;
    unsigned dst = (unsigned)__cvta_generic_to_shared(
        &srow[(slot0 + rl) * ROWSTRIDE + chunk * 4]);
    asm volatile("cp.async.cg.shared.global [%0], [%1], 16;\n"
                 :: "r"(dst), "l"(src) : "memory");
}

__device__ __forceinline__ void commit_group() {
    asm volatile("cp.async.commit_group;\n" ::: "memory");
}
__device__ __forceinline__ void wait_group1() {
    asm volatile("cp.async.wait_group 1;\n" ::: "memory");
}

// horizontal filters for one staged row: returns (lo@2c, lo@2c+1, hi@2c, hi@2c+1)
__device__ __forceinline__ float4 hfilt_row(const float* __restrict__ row, int c, bool edge) {
    float w0, w1, w2, w3, w4, w5, w6, w7;  // cols 2c-3 .. 2c+4
    if (!edge) {
        const float2 pa = *(const float2*)(row + 2*c - 4);
        const float2 pb = *(const float2*)(row + 2*c - 2);
        const float2 pc = *(const float2*)(row + 2*c    );
        const float2 pd = *(const float2*)(row + 2*c + 2);
        const float2 pe = *(const float2*)(row + 2*c + 4);
        w0 = pa.y; w1 = pb.x; w2 = pb.y; w3 = pc.x;
        w4 = pc.y; w5 = pd.x; w6 = pd.y; w7 = pe.x;
    } else {
        w0 = row[refl(2*c - 3)];
        w1 = row[refl(2*c - 2)];
        w2 = row[refl(2*c - 1)];
        w3 = row[refl(2*c    )];
        w4 = row[refl(2*c + 1)];
        w5 = row[refl(2*c + 2)];
        w6 = row[refl(2*c + 3)];
        w7 = row[refl(2*c + 4)];
    }
    float4 v;
    v.x = G0*w1 + G1*w2 + G2*w3 + G3*w4 + G4*w5;
    v.y = G0*w2 + G1*w3 + G2*w4 + G3*w5 + G4*w6;
    v.z = H0*w0 + H1*w1 + H2*w2 + H3*w3 + H4*w4 + H5*w5 + H6*w6;
    v.w = H0*w1 + H1*w2 + H2*w3 + H3*w4 + H4*w5 + H5*w6 + H6*w7;
    return v;
}

__global__ __launch_bounds__(NTHREADS, 4) void scat_kernel(
    const float* __restrict__ x,
    float* __restrict__ out)
{
    __shared__ float srow[NSLOT * ROWSTRIDE];

    const int c   = threadIdx.x;            // pair-column 0..255
    const int img = blockIdx.z;             // b*3 + ch
    const int OY0 = blockIdx.y * TILE_OY;
    const float* __restrict__ xin = x + (size_t)img * (512*512);
    const bool edge = (c < 2) || (c > 253);

    const int b_  = img / 3;
    const int ch_ = img % 3;
    size_t obase = (((size_t)b_*21 + ch_)*256 + OY0)*256 + c;
    const size_t cs = (size_t)3*256*256;

    const int R = 2*OY0 - 3;                // first input row of window

    // ---- prologue: stage rows R..R+7 (4 groups), hfilt rows R..R+5 ----
    stage2(xin, srow, c, 0, R + 0); commit_group();
    stage2(xin, srow, c, 2, R + 2); commit_group();
    stage2(xin, srow, c, 4, R + 4); commit_group();
    stage2(xin, srow, c, 6, R + 6); commit_group();
    wait_group1();                          // slots 0..5 ready (g3 may be in flight)
    __syncthreads();

    float4 ring[NSLOT];
    #pragma unroll
    for (int j = 0; j < 6; j++)
        ring[j] = hfilt_row(&srow[j * ROWSTRIDE], c, edge);
    __syncthreads();                        // protect slots 0..5 before overwrite

    #pragma unroll 1
    for (int k4 = 0; k4 < TILE_OY/4; ++k4) {
        #pragma unroll
        for (int u = 0; u < 4; ++u) {
            const int oy = k4*4 + u;

            // prefetch rows 2oy+8, 2oy+9 for the next iteration
            stage2(xin, srow, c, (2*oy + 8) & (NSLOT-1), R + 2*oy + 8);
            commit_group();
            wait_group1();                  // rows 2oy+6, 2oy+7 now staged
            __syncthreads();

            // complete the 8-row window in the register ring
            ring[(6 + 2*u) & 7] = hfilt_row(&srow[((2*oy + 6) & (NSLOT-1)) * ROWSTRIDE], c, edge);
            ring[(7 + 2*u) & 7] = hfilt_row(&srow[((2*oy + 7) & (NSLOT-1)) * ROWSTRIDE], c, edge);

            const float4 q0 = ring[(2*u + 0) & 7];
            const float4 q1 = ring[(2*u + 1) & 7];
            const float4 q2 = ring[(2*u + 2) & 7];
            const float4 q3 = ring[(2*u + 3) & 7];
            const float4 q4 = ring[(2*u + 4) & 7];
            const float4 q5 = ring[(2*u + 5) & 7];
            const float4 q6 = ring[(2*u + 6) & 7];
            const float4 q7 = ring[(2*u + 7) & 7];

            // ---- lo plane (.x,.y): LL (pooled), LH -> m15, m165 ----
            float LH0x = H0*q0.x + H1*q1.x + H2*q2.x + H3*q3.x + H4*q4.x + H5*q5.x + H6*q6.x;
            float LH0y = H0*q0.y + H1*q1.y + H2*q2.y + H3*q3.y + H4*q4.y + H5*q5.y + H6*q6.y;
            float LH1x = H0*q1.x + H1*q2.x + H2*q3.x + H3*q4.x + H4*q5.x + H5*q6.x + H6*q7.x;
            float LH1y = H0*q1.y + H1*q2.y + H2*q3.y + H3*q4.y + H4*q5.y + H5*q6.y + H6*q7.y;
            float LL0x = G0*q1.x + G1*q2.x + G2*q3.x + G3*q4.x + G4*q5.x;
            float LL0y = G0*q1.y + G1*q2.y + G2*q3.y + G3*q4.y + G4*q5.y;
            float LL1x = G0*q2.x + G1*q3.x + G2*q4.x + G3*q5.x + G4*q6.x;
            float LL1y = G0*q2.y + G1*q3.y + G2*q4.y + G3*q5.y + G4*q6.y;

            const float llp  = 0.25f*(LL0x + LL0y + LL1x + LL1y);
            const float m15  = bandmag(LH0x - LH1y, LH0y + LH1x);
            const float m165 = bandmag(LH0x + LH1y, LH0y - LH1x);

            // ---- hi plane (.z,.w): HL -> m75, m105 ; HH -> m45, m135 ----
            float HH0x = H0*q0.z + H1*q1.z + H2*q2.z + H3*q3.z + H4*q4.z + H5*q5.z + H6*q6.z;
            float HH0y = H0*q0.w + H1*q1.w + H2*q2.w + H3*q3.w + H4*q4.w + H5*q5.w + H6*q6.w;
            float HH1x = H0*q1.z + H1*q2.z + H2*q3.z + H3*q4.z + H4*q5.z + H5*q6.z + H6*q7.z;
            float HH1y = H0*q1.w + H1*q2.w + H2*q3.w + H3*q4.w + H4*q5.w + H5*q6.w + H6*q7.w;
            float HL0x = G0*q1.z + G1*q2.z + G2*q3.z + G3*q4.z + G4*q5.z;
            float HL0y = G0*q1.w + G1*q2.w + G2*q3.w + G3*q4.w + G4*q5.w;
            float HL1x = G0*q2.z + G1*q3.z + G2*q4.z + G3*q5.z + G4*q6.z;
            float HL1y = G0*q2.w + G1*q3.w + G2*q4.w + G3*q5.w + G4*q6.w;

            const float m45  = bandmag(HH0x - HH1y, HH0y + HH1x);
            const float m135 = bandmag(HH0x + HH1y, HH0y - HH1x);
            const float m75  = bandmag(HL0x - HL1y, HL0y + HL1x);
            const float m105 = bandmag(HL0x + HL1y, HL0y - HL1x);

            float* o = out + obase + (size_t)oy*256;
            o[0]    = llp;
            o[1*cs] = m15;
            o[2*cs] = m45;
            o[3*cs] = m75;
            o[4*cs] = m105;
            o[5*cs] = m135;
            o[6*cs] = m165;
        }
    }
}

extern "C" void kernel_launch(void* const* d_in, const int* in_sizes, int n_in,
                              void* d_out, int out_size) {
    const float* x = (const float*)d_in[0];
    float* out = (float*)d_out;

    dim3 grid(1, 256/TILE_OY, 96);          // (1, 16, 96)
    scat_kernel<<<grid, NTHREADS>>>(x, out);
}

// round 7
// speedup vs baseline: 3.1290x; 1.2368x over previous
#include <cuda_runtime.h>
#include <math.h>

// Fused DTCWT scattering layer, round 7: cp.async row pipeline + packed f32x2 math.
//  - 8-slot smem ring of raw input rows (cp.async.cg, 1 op/thread/iter)
//  - horizontal + vertical filters use symmetric-tap + f32x2 packed ops
//  - register ring of packed quads; vertical pair-sums shared between H and G bands
// x: (32,3,512,512) f32 -> out: (32,21,256,256) f32

#define TILE_OY 16
#define NTHREADS 256
#define ROWSTRIDE 520
#define NSLOT 8

// h0: [-0.05, 0.25, 0.6, 0.25, -0.05]           (symmetric: G0=G4, G1=G3)
#define G0 (-0.05f)
#define G1 (0.25f)
#define G2 (0.6f)
// h1: [-0.0107143, 0.0535714, 0.2607143, -0.6071429, ...] (symmetric)
#define H0 (-0.0107143f)
#define H1 (0.0535714f)
#define H2 (0.2607143f)
#define H3 (-0.6071429f)

typedef unsigned long long u64;

__device__ __forceinline__ u64 pk(float lo, float hi) {
    u64 r; asm("mov.b64 %0,{%1,%2};" : "=l"(r) : "f"(lo), "f"(hi)); return r;
}
__device__ __forceinline__ void upk(u64 v, float& a, float& b) {
    asm("mov.b64 {%0,%1},%2;" : "=f"(a), "=f"(b) : "l"(v));
}
__device__ __forceinline__ u64 add2(u64 a, u64 b) {
    u64 r; asm("add.rn.f32x2 %0,%1,%2;" : "=l"(r) : "l"(a), "l"(b)); return r;
}
__device__ __forceinline__ u64 mul2(u64 a, u64 b) {
    u64 r; asm("mul.rn.f32x2 %0,%1,%2;" : "=l"(r) : "l"(a), "l"(b)); return r;
}
__device__ __forceinline__ u64 fma2(u64 a, u64 b, u64 c) {
    u64 r; asm("fma.rn.f32x2 %0,%1,%2,%3;" : "=l"(r) : "l"(a), "l"(b), "l"(c)); return r;
}

__device__ __forceinline__ int refl(int i) {
    i = (i < 0) ? (-i - 1) : i;
    return (i > 511) ? (1023 - i) : i;
}

__device__ __forceinline__ float sqrt_approx(float v) {
    float r; asm("sqrt.approx.f32 %0, %1;" : "=f"(r) : "f"(v)); return r;
}
// band value = sqrt((re^2+im^2)/2 + 1e-4) - 0.01  (1/sqrt2 folded in)
__device__ __forceinline__ float bandmag(float re, float im) {
    return sqrt_approx(0.5f * fmaf(re, re, fmaf(im, im, 2e-4f))) - 0.01f;
}

__device__ __forceinline__ void stage2(const float* __restrict__ xin, float* srow,
                                       int c, int slot0, int grow0) {
    const int rl    = c >> 7;
    const int chunk = c & 127;
    const int gy    = refl(grow0 + rl);
    const float* src = xin + (size_t)gy * 512 + chunk * 4;
    unsigned dst = (unsigned)__cvta_generic_to_shared(
        &srow[(slot0 + rl) * ROWSTRIDE + chunk * 4]);
    asm volatile("cp.async.cg.shared.global [%0], [%1], 16;\n" :: "r"(dst), "l"(src) : "memory");
}
__device__ __forceinline__ void commit_group() {
    asm volatile("cp.async.commit_group;\n" ::: "memory");
}
__device__ __forceinline__ void wait_group1() {
    asm volatile("cp.async.wait_group 1;\n" ::: "memory");
}

// horizontal filters (packed): outputs loxy=(lo@2c,lo@2c+1), hizw=(hi@2c,hi@2c+1)
__device__ __forceinline__ void hfilt_row(const float* __restrict__ row, int c, bool edge,
                                          u64 g0p, u64 g1p, u64 g2p,
                                          u64 h0p, u64 h1p, u64 h2p, u64 h3p,
                                          u64& loxy, u64& hizw) {
    u64 S1, S2, T1, PC;                 // (w1+w5,w2+w6) (w2+w4,w3+w5) (w0+w6,w1+w7) (w3,w4)
    if (!edge) {
        const float* p = row + 2*c;
        const u64 PA = *(const u64*)(p - 4);   // (w-1,w0)
        const u64 PB = *(const u64*)(p - 2);   // (w1,w2)
        PC           = *(const u64*)(p    );   // (w3,w4)
        const u64 PD = *(const u64*)(p + 2);   // (w5,w6)
        const u64 PE = *(const u64*)(p + 4);   // (w7,w8)
        float am, a0, b1, b2, c3, c4, d5, d6, e7, e8;
        upk(PA, am, a0); upk(PB, b1, b2); upk(PC, c3, c4);
        upk(PD, d5, d6); upk(PE, e7, e8);
        S1 = add2(PB, PD);                      // (w1+w5, w2+w6)
        S2 = add2(pk(b2, c3), pk(c4, d5));      // (w2+w4, w3+w5)
        T1 = add2(pk(a0, b1), pk(d6, e7));      // (w0+w6, w1+w7)
    } else {
        const float w0 = row[refl(2*c - 3)];
        const float w1 = row[refl(2*c - 2)];
        const float w2 = row[refl(2*c - 1)];
        const float w3 = row[refl(2*c    )];
        const float w4 = row[refl(2*c + 1)];
        const float w5 = row[refl(2*c + 2)];
        const float w6 = row[refl(2*c + 3)];
        const float w7 = row[refl(2*c + 4)];
        S1 = pk(w1 + w5, w2 + w6);
        S2 = pk(w2 + w4, w3 + w5);
        T1 = pk(w0 + w6, w1 + w7);
        PC = pk(w3, w4);
    }
    loxy = fma2(S1, g0p, fma2(S2, g1p, mul2(PC, g2p)));
    hizw = fma2(T1, h0p, fma2(S1, h1p, fma2(S2, h2p, mul2(PC, h3p))));
}

__global__ __launch_bounds__(NTHREADS, 3) void scat_kernel(
    const float* __restrict__ x,
    float* __restrict__ out)
{
    __shared__ float srow[NSLOT * ROWSTRIDE];

    const int c   = threadIdx.x;
    const int img = blockIdx.z;
    const int OY0 = blockIdx.y * TILE_OY;
    const float* __restrict__ xin = x + (size_t)img * (512*512);
    const bool edge = (c < 2) || (c > 253);

    const int b_  = img / 3;
    const int ch_ = img % 3;
    size_t obase = (((size_t)b_*21 + ch_)*256 + OY0)*256 + c;
    const size_t cs = (size_t)3*256*256;

    // packed symmetric coefficients
    const u64 g0p = pk(G0, G0), g1p = pk(G1, G1), g2p = pk(G2, G2);
    const u64 h0p = pk(H0, H0), h1p = pk(H1, H1), h2p = pk(H2, H2), h3p = pk(H3, H3);

    const int R = 2*OY0 - 3;

    stage2(xin, srow, c, 0, R + 0); commit_group();
    stage2(xin, srow, c, 2, R + 2); commit_group();
    stage2(xin, srow, c, 4, R + 4); commit_group();
    stage2(xin, srow, c, 6, R + 6); commit_group();
    wait_group1();
    __syncthreads();

    u64 rxy[NSLOT], rzw[NSLOT];
    #pragma unroll
    for (int j = 0; j < 6; j++)
        hfilt_row(&srow[j * ROWSTRIDE], c, edge, g0p, g1p, g2p, h0p, h1p, h2p, h3p,
                  rxy[j], rzw[j]);
    __syncthreads();

    #pragma unroll 1
    for (int k4 = 0; k4 < TILE_OY/4; ++k4) {
        #pragma unroll
        for (int u = 0; u < 4; ++u) {
            const int oy = k4*4 + u;

            stage2(xin, srow, c, (2*oy + 8) & (NSLOT-1), R + 2*oy + 8);
            commit_group();
            wait_group1();
            __syncthreads();

            hfilt_row(&srow[((2*oy + 6) & (NSLOT-1)) * ROWSTRIDE], c, edge,
                      g0p, g1p, g2p, h0p, h1p, h2p, h3p,
                      rxy[(6 + 2*u) & 7], rzw[(6 + 2*u) & 7]);
            hfilt_row(&srow[((2*oy + 7) & (NSLOT-1)) * ROWSTRIDE], c, edge,
                      g0p, g1p, g2p, h0p, h1p, h2p, h3p,
                      rxy[(7 + 2*u) & 7], rzw[(7 + 2*u) & 7]);

            float llp, m15, m165, m45, m135, m75, m105;

            #pragma unroll
            for (int plane = 0; plane < 2; plane++) {
                const u64* r = plane ? rzw : rxy;
                const u64 r0 = r[(2*u + 0) & 7], r1 = r[(2*u + 1) & 7];
                const u64 r2 = r[(2*u + 2) & 7], r3 = r[(2*u + 3) & 7];
                const u64 r4 = r[(2*u + 4) & 7], r5 = r[(2*u + 5) & 7];
                const u64 r6 = r[(2*u + 6) & 7], r7 = r[(2*u + 7) & 7];

                // shared pair-sums (symmetric taps)
                const u64 A06 = add2(r0, r6), A15 = add2(r1, r5), A24 = add2(r2, r4);
                const u64 A17 = add2(r1, r7), A26 = add2(r2, r6), A35 = add2(r3, r5);

                // 7-tap band (LH for lo plane / HH for hi plane)
                const u64 F0 = fma2(A06, h0p, fma2(A15, h1p, fma2(A24, h2p, mul2(r3, h3p))));
                const u64 F1 = fma2(A17, h0p, fma2(A26, h1p, fma2(A35, h2p, mul2(r4, h3p))));
                // 5-tap band (LL for lo plane / HL for hi plane) reuses A-sums
                const u64 E0 = fma2(A15, g0p, fma2(A24, g1p, mul2(r3, g2p)));
                const u64 E1 = fma2(A26, g0p, fma2(A35, g1p, mul2(r4, g2p)));

                float f0x, f0y, f1x, f1y;
                upk(F0, f0x, f0y); upk(F1, f1x, f1y);

                if (plane == 0) {
                    m15  = bandmag(f0x - f1y, f0y + f1x);
                    m165 = bandmag(f0x + f1y, f0y - f1x);
                    float s0, s1;
                    upk(add2(E0, E1), s0, s1);
                    llp = 0.25f * (s0 + s1);
                } else {
                    m45  = bandmag(f0x - f1y, f0y + f1x);
                    m135 = bandmag(f0x + f1y, f0y - f1x);
                    float e0x, e0y, e1x, e1y;
                    upk(E0, e0x, e0y); upk(E1, e1x, e1y);
                    m75  = bandmag(e0x - e1y, e0y + e1x);
                    m105 = bandmag(e0x + e1y, e0y - e1x);
                }
            }

            float* o = out + obase + (size_t)oy*256;
            o[0]    = llp;
            o[1*cs] = m15;
            o[2*cs] = m45;
            o[3*cs] = m75;
            o[4*cs] = m105;
            o[5*cs] = m135;
            o[6*cs] = m165;
        }
    }
}

extern "C" void kernel_launch(void* const* d_in, const int* in_sizes, int n_in,
                              void* d_out, int out_size) {
    const float* x = (const float*)d_in[0];
    float* out = (float*)d_out;

    dim3 grid(1, 256/TILE_OY, 96);          // (1, 16, 96)
    scat_kernel<<<grid, NTHREADS>>>(x, out);
}

// round 8
// speedup vs baseline: 3.1950x; 1.0211x over previous
#include <cuda_runtime.h>
#include <math.h>

// Fused DTCWT scattering layer, round 8:
//  - cp.async row pipeline: 16-slot smem ring, 4 rows staged per iteration,
//    prefetch distance 2 iterations (8 rows), wait_group 2
//  - 2 output rows per barrier (8 barriers/tile instead of 16)
//  - packed f32x2 filters with symmetric-tap sharing; register quad ring of 8
// x: (32,3,512,512) f32 -> out: (32,21,256,256) f32

#define TILE_OY 16
#define NTHREADS 256
#define ROWSTRIDE 520
#define NSLOT 16

// h0: [-0.05, 0.25, 0.6, 0.25, -0.05]  (symmetric)
#define G0 (-0.05f)
#define G1 (0.25f)
#define G2 (0.6f)
// h1: [-0.0107143, 0.0535714, 0.2607143, -0.6071429, ...] (symmetric)
#define H0 (-0.0107143f)
#define H1 (0.0535714f)
#define H2 (0.2607143f)
#define H3 (-0.6071429f)

typedef unsigned long long u64;

__device__ __forceinline__ u64 pk(float lo, float hi) {
    u64 r; asm("mov.b64 %0,{%1,%2};" : "=l"(r) : "f"(lo), "f"(hi)); return r;
}
__device__ __forceinline__ void upk(u64 v, float& a, float& b) {
    asm("mov.b64 {%0,%1},%2;" : "=f"(a), "=f"(b) : "l"(v));
}
__device__ __forceinline__ u64 add2(u64 a, u64 b) {
    u64 r; asm("add.rn.f32x2 %0,%1,%2;" : "=l"(r) : "l"(a), "l"(b)); return r;
}
__device__ __forceinline__ u64 mul2(u64 a, u64 b) {
    u64 r; asm("mul.rn.f32x2 %0,%1,%2;" : "=l"(r) : "l"(a), "l"(b)); return r;
}
__device__ __forceinline__ u64 fma2(u64 a, u64 b, u64 c) {
    u64 r; asm("fma.rn.f32x2 %0,%1,%2,%3;" : "=l"(r) : "l"(a), "l"(b), "l"(c)); return r;
}

__device__ __forceinline__ int refl(int i) {
    i = (i < 0) ? (-i - 1) : i;
    return (i > 511) ? (1023 - i) : i;
}
__device__ __forceinline__ float sqrt_approx(float v) {
    float r; asm("sqrt.approx.f32 %0, %1;" : "=f"(r) : "f"(v)); return r;
}
// band value = sqrt((re^2+im^2)/2 + 1e-4) - 0.01  (1/sqrt2 folded in)
__device__ __forceinline__ float bandmag(float re, float im) {
    return sqrt_approx(0.5f * fmaf(re, re, fmaf(im, im, 2e-4f))) - 0.01f;
}

// stage rows R+m, R+m+1 into slots m&15, (m+1)&15 (one 16B cp.async per thread)
__device__ __forceinline__ void stage2(const float* __restrict__ xin, float* srow,
                                       int c, int R, int m) {
    const int rl    = c >> 7;
    const int chunk = c & 127;
    const int gy    = refl(R + m + rl);
    const float* src = xin + (size_t)gy * 512 + chunk * 4;
    unsigned dst = (unsigned)__cvta_generic_to_shared(
        &srow[((m + rl) & (NSLOT-1)) * ROWSTRIDE + chunk * 4]);
    asm volatile("cp.async.cg.shared.global [%0], [%1], 16;\n" :: "r"(dst), "l"(src) : "memory");
}
__device__ __forceinline__ void commit_group() {
    asm volatile("cp.async.commit_group;\n" ::: "memory");
}
__device__ __forceinline__ void wait_group2() {
    asm volatile("cp.async.wait_group 2;\n" ::: "memory");
}

// horizontal filters (packed): loxy=(lo@2c,lo@2c+1), hizw=(hi@2c,hi@2c+1)
__device__ __forceinline__ void hfilt_row(const float* __restrict__ row, int c, bool edge,
                                          u64 g0p, u64 g1p, u64 g2p,
                                          u64 h0p, u64 h1p, u64 h2p, u64 h3p,
                                          u64& loxy, u64& hizw) {
    u64 S1, S2, T1, PC;
    if (!edge) {
        const float* p = row + 2*c;
        const u64 PA = *(const u64*)(p - 4);   // (w-1,w0)
        const u64 PB = *(const u64*)(p - 2);   // (w1,w2)
        PC           = *(const u64*)(p    );   // (w3,w4)
        const u64 PD = *(const u64*)(p + 2);   // (w5,w6)
        const u64 PE = *(const u64*)(p + 4);   // (w7,w8)
        float am, a0, b1, b2, c3, c4, d5, d6, e7, e8;
        upk(PA, am, a0); upk(PB, b1, b2); upk(PC, c3, c4);
        upk(PD, d5, d6); upk(PE, e7, e8);
        S1 = add2(PB, PD);                      // (w1+w5, w2+w6)
        S2 = add2(pk(b2, c3), pk(c4, d5));      // (w2+w4, w3+w5)
        T1 = add2(pk(a0, b1), pk(d6, e7));      // (w0+w6, w1+w7)
    } else {
        const float w0 = row[refl(2*c - 3)];
        const float w1 = row[refl(2*c - 2)];
        const float w2 = row[refl(2*c - 1)];
        const float w3 = row[refl(2*c    )];
        const float w4 = row[refl(2*c + 1)];
        const float w5 = row[refl(2*c + 2)];
        const float w6 = row[refl(2*c + 3)];
        const float w7 = row[refl(2*c + 4)];
        S1 = pk(w1 + w5, w2 + w6);
        S2 = pk(w2 + w4, w3 + w5);
        T1 = pk(w0 + w6, w1 + w7);
        PC = pk(w3, w4);
    }
    loxy = fma2(S1, g0p, fma2(S2, g1p, mul2(PC, g2p)));
    hizw = fma2(T1, h0p, fma2(S1, h1p, fma2(S2, h2p, mul2(PC, h3p))));
}

__global__ __launch_bounds__(NTHREADS, 3) void scat_kernel(
    const float* __restrict__ x,
    float* __restrict__ out)
{
    __shared__ float srow[NSLOT * ROWSTRIDE];

    const int c   = threadIdx.x;
    const int img = blockIdx.z;
    const int OY0 = blockIdx.y * TILE_OY;
    const float* __restrict__ xin = x + (size_t)img * (512*512);
    const bool edge = (c < 2) || (c > 253);

    const int b_  = img / 3;
    const int ch_ = img % 3;
    size_t obase = (((size_t)b_*21 + ch_)*256 + OY0)*256 + c;
    const size_t cs = (size_t)3*256*256;

    const u64 g0p = pk(G0, G0), g1p = pk(G1, G1), g2p = pk(G2, G2);
    const u64 h0p = pk(H0, H0), h1p = pk(H1, H1), h2p = pk(H2, H2), h3p = pk(H3, H3);

    const int R = 2*OY0 - 3;

    // ---- prologue: stage rows R..R+13 in 3 groups ----
    stage2(xin, srow, c, R, 0); stage2(xin, srow, c, R, 2); stage2(xin, srow, c, R, 4);
    commit_group();                                  // P0: rows 0..5
    stage2(xin, srow, c, R, 6); stage2(xin, srow, c, R, 8);
    commit_group();                                  // P1: rows 6..9
    stage2(xin, srow, c, R, 10); stage2(xin, srow, c, R, 12);
    commit_group();                                  // P2: rows 10..13
    wait_group2();                                   // P0 complete
    __syncthreads();

    u64 rxy[8], rzw[8];
    #pragma unroll
    for (int j = 0; j < 6; j++)
        hfilt_row(&srow[j * ROWSTRIDE], c, edge, g0p, g1p, g2p, h0p, h1p, h2p, h3p,
                  rxy[j], rzw[j]);
    __syncthreads();                                 // protect slots 0..5 (iter0 writes slot 0,1)

    #pragma unroll 1
    for (int ib = 0; ib < 4; ++ib) {
        #pragma unroll
        for (int pp = 0; pp < 2; ++pp) {
            const int i  = 2*ib + pp;                // pipeline iteration 0..7
            const int m4 = 4*i;

            // prefetch rows m=14+4i .. 17+4i (distance-2)
            stage2(xin, srow, c, R, 14 + m4);
            stage2(xin, srow, c, R, 16 + m4);
            commit_group();
            wait_group2();                           // rows <= 9+4i staged
            __syncthreads();

            // ring slots rotate by 4 per iteration: row R+m -> slot m&7
            const int s = 4*pp;                      // compile-time base rotation

            hfilt_row(&srow[((6 + m4) & (NSLOT-1)) * ROWSTRIDE], c, edge,
                      g0p, g1p, g2p, h0p, h1p, h2p, h3p,
                      rxy[(s + 6) & 7], rzw[(s + 6) & 7]);
            hfilt_row(&srow[((7 + m4) & (NSLOT-1)) * ROWSTRIDE], c, edge,
                      g0p, g1p, g2p, h0p, h1p, h2p, h3p,
                      rxy[(s + 7) & 7], rzw[(s + 7) & 7]);

            #pragma unroll
            for (int half = 0; half < 2; ++half) {   // half=0 -> oy=2i, half=1 -> oy=2i+1
                if (half == 1) {                     // bring in rows 8+4i, 9+4i
                    hfilt_row(&srow[((8 + m4) & (NSLOT-1)) * ROWSTRIDE], c, edge,
                              g0p, g1p, g2p, h0p, h1p, h2p, h3p,
                              rxy[(s + 8) & 7], rzw[(s + 8) & 7]);
                    hfilt_row(&srow[((9 + m4) & (NSLOT-1)) * ROWSTRIDE], c, edge,
                              g0p, g1p, g2p, h0p, h1p, h2p, h3p,
                              rxy[(s + 9) & 7], rzw[(s + 9) & 7]);
                }
                const int w0 = s + 2*half;           // window base (compile-time)

                float llp, m15, m165, m45, m135, m75, m105;
                #pragma unroll
                for (int plane = 0; plane < 2; plane++) {
                    const u64* r = plane ? rzw : rxy;
                    const u64 r0 = r[(w0 + 0) & 7], r1 = r[(w0 + 1) & 7];
                    const u64 r2 = r[(w0 + 2) & 7], r3 = r[(w0 + 3) & 7];
                    const u64 r4 = r[(w0 + 4) & 7], r5 = r[(w0 + 5) & 7];
                    const u64 r6 = r[(w0 + 6) & 7], r7 = r[(w0 + 7) & 7];

                    const u64 A06 = add2(r0, r6), A15 = add2(r1, r5), A24 = add2(r2, r4);
                    const u64 A17 = add2(r1, r7), A26 = add2(r2, r6), A35 = add2(r3, r5);

                    const u64 F0 = fma2(A06, h0p, fma2(A15, h1p, fma2(A24, h2p, mul2(r3, h3p))));
                    const u64 F1 = fma2(A17, h0p, fma2(A26, h1p, fma2(A35, h2p, mul2(r4, h3p))));
                    const u64 E0 = fma2(A15, g0p, fma2(A24, g1p, mul2(r3, g2p)));
                    const u64 E1 = fma2(A26, g0p, fma2(A35, g1p, mul2(r4, g2p)));

                    float f0x, f0y, f1x, f1y;
                    upk(F0, f0x, f0y); upk(F1, f1x, f1y);

                    if (plane == 0) {
                        m15  = bandmag(f0x - f1y, f0y + f1x);
                        m165 = bandmag(f0x + f1y, f0y - f1x);
                        float s0, s1;
                        upk(add2(E0, E1), s0, s1);
                        llp = 0.25f * (s0 + s1);
                    } else {
                        m45  = bandmag(f0x - f1y, f0y + f1x);
                        m135 = bandmag(f0x + f1y, f0y - f1x);
                        float e0x, e0y, e1x, e1y;
                        upk(E0, e0x, e0y); upk(E1, e1x, e1y);
                        m75  = bandmag(e0x - e1y, e0y + e1x);
                        m105 = bandmag(e0x + e1y, e0y - e1x);
                    }
                }

                float* o = out + obase + (size_t)(2*i + half)*256;
                o[0]    = llp;
                o[1*cs] = m15;
                o[2*cs] = m45;
                o[3*cs] = m75;
                o[4*cs] = m105;
                o[5*cs] = m135;
                o[6*cs] = m165;
            }
        }
    }
}

extern "C" void kernel_launch(void* const* d_in, const int* in_sizes, int n_in,
                              void* d_out, int out_size) {
    const float* x = (const float*)d_in[0];
    float* out = (float*)d_out;

    dim3 grid(1, 256/TILE_OY, 96);          // (1, 16, 96)
    scat_kernel<<<grid, NTHREADS>>>(x, out);
}

// round 9
// speedup vs baseline: 3.3339x; 1.0435x over previous
#include <cuda_runtime.h>
#include <math.h>

// Fused DTCWT scattering layer, round 9:
//  - 32-slot smem ring of PADDED rows (4+512+4 reflected pads) -> uniform branch-free hfilt
//  - 4 output rows per barrier (4 barriers/tile); ring-register indices fully compile-time
//  - exact staging m=0..37 per tile; pads filled via LDG->STS during stage (no extra sync)
//  - packed f32x2 filters with symmetric-tap sharing
// x: (32,3,512,512) f32 -> out: (32,21,256,256) f32

#define TILE_OY 16
#define NTHREADS 256
#define ROWSTRIDE 524              // 4 pad | 512 data | 4 pad | 4 spare  (floats)
#define NSLOT 32
#define SMEM_BYTES (NSLOT*ROWSTRIDE*4)   // 67072

// h0: [-0.05, 0.25, 0.6, 0.25, -0.05]  (symmetric)
#define G0 (-0.05f)
#define G1 (0.25f)
#define G2 (0.6f)
// h1: [-0.0107143, 0.0535714, 0.2607143, -0.6071429, ...] (symmetric)
#define H0 (-0.0107143f)
#define H1 (0.0535714f)
#define H2 (0.2607143f)
#define H3 (-0.6071429f)

typedef unsigned long long u64;

__device__ __forceinline__ u64 pk(float lo, float hi) {
    u64 r; asm("mov.b64 %0,{%1,%2};" : "=l"(r) : "f"(lo), "f"(hi)); return r;
}
__device__ __forceinline__ void upk(u64 v, float& a, float& b) {
    asm("mov.b64 {%0,%1},%2;" : "=f"(a), "=f"(b) : "l"(v));
}
__device__ __forceinline__ u64 add2(u64 a, u64 b) {
    u64 r; asm("add.rn.f32x2 %0,%1,%2;" : "=l"(r) : "l"(a), "l"(b)); return r;
}
__device__ __forceinline__ u64 mul2(u64 a, u64 b) {
    u64 r; asm("mul.rn.f32x2 %0,%1,%2;" : "=l"(r) : "l"(a), "l"(b)); return r;
}
__device__ __forceinline__ u64 fma2(u64 a, u64 b, u64 c) {
    u64 r; asm("fma.rn.f32x2 %0,%1,%2,%3;" : "=l"(r) : "l"(a), "l"(b), "l"(c)); return r;
}

__device__ __forceinline__ int refl(int i) {
    i = (i < 0) ? (-i - 1) : i;
    return (i > 511) ? (1023 - i) : i;
}
__device__ __forceinline__ float sqrt_approx(float v) {
    float r; asm("sqrt.approx.f32 %0, %1;" : "=f"(r) : "f"(v)); return r;
}
// band value = sqrt((re^2+im^2)/2 + 1e-4) - 0.01  (1/sqrt2 folded in)
__device__ __forceinline__ float bandmag(float re, float im) {
    return sqrt_approx(0.5f * fmaf(re, re, fmaf(im, im, 2e-4f))) - 0.01f;
}

__device__ __forceinline__ void commit_group() {
    asm volatile("cp.async.commit_group;\n" ::: "memory");
}
__device__ __forceinline__ void wait_group1() {
    asm volatile("cp.async.wait_group 1;\n" ::: "memory");
}

// stage nr rows starting at window-index m0 (nr even): nr/2 cp.async per thread,
// plus reflected pads (8 per row) filled straight from global by threads t < 8*nr.
__device__ __forceinline__ void stage_rows(const float* __restrict__ xin, float* srow,
                                           int t, int R, int m0, int nr) {
    const int rl = t >> 7, chunk = t & 127;
    #pragma unroll
    for (int j = 0; j < 7; ++j) {
        if (j >= nr/2) break;
        const int m  = m0 + 2*j + rl;
        const int gy = refl(R + m);
        const float* src = xin + (size_t)gy*512 + chunk*4;
        unsigned dst = (unsigned)__cvta_generic_to_shared(
            &srow[(m & (NSLOT-1))*ROWSTRIDE + 4 + chunk*4]);
        asm volatile("cp.async.cg.shared.global [%0], [%1], 16;\n" :: "r"(dst), "l"(src) : "memory");
    }
    if (t < 8*nr) {
        const int k = t >> 3, pp = t & 7;
        const int m  = m0 + k;
        const int gy = refl(R + m);
        float* rb = &srow[(m & (NSLOT-1))*ROWSTRIDE];
        if (pp < 4) rb[pp]       = __ldg(&xin[(size_t)gy*512 + (3 - pp)]);   // cols -4..-1
        else        rb[512 + pp] = __ldg(&xin[(size_t)gy*512 + (515 - pp)]); // cols 512..515
    }
}

// branch-free horizontal filters: p = row_base + 4 + 2c (pads guarantee p-4..p+5 valid)
__device__ __forceinline__ void hfilt_row(const float* __restrict__ p,
                                          u64 g0p, u64 g1p, u64 g2p,
                                          u64 h0p, u64 h1p, u64 h2p, u64 h3p,
                                          u64& loxy, u64& hizw) {
    const u64 PA = *(const u64*)(p - 4);   // (w-1,w0)
    const u64 PB = *(const u64*)(p - 2);   // (w1,w2)
    const u64 PC = *(const u64*)(p    );   // (w3,w4)
    const u64 PD = *(const u64*)(p + 2);   // (w5,w6)
    const u64 PE = *(const u64*)(p + 4);   // (w7,w8)
    float am, a0, b1, b2, c3, c4, d5, d6, e7, e8;
    upk(PA, am, a0); upk(PB, b1, b2); upk(PC, c3, c4);
    upk(PD, d5, d6); upk(PE, e7, e8);
    const u64 S1 = add2(PB, PD);                  // (w1+w5, w2+w6)
    const u64 S2 = add2(pk(b2, c3), pk(c4, d5));  // (w2+w4, w3+w5)
    const u64 T1 = add2(pk(a0, b1), pk(d6, e7));  // (w0+w6, w1+w7)
    loxy = fma2(S1, g0p, fma2(S2, g1p, mul2(PC, g2p)));
    hizw = fma2(T1, h0p, fma2(S1, h1p, fma2(S2, h2p, mul2(PC, h3p))));
}

__global__ __launch_bounds__(NTHREADS, 3) void scat_kernel(
    const float* __restrict__ x,
    float* __restrict__ out)
{
    extern __shared__ float srow[];        // [NSLOT][ROWSTRIDE]

    const int c   = threadIdx.x;           // pair-column 0..255
    const int img = blockIdx.z;
    const int OY0 = blockIdx.y * TILE_OY;
    const float* __restrict__ xin = x + (size_t)img * (512*512);

    const int b_  = img / 3;
    const int ch_ = img % 3;
    size_t obase = (((size_t)b_*21 + ch_)*256 + OY0)*256 + c;
    const size_t cs = (size_t)3*256*256;

    const u64 g0p = pk(G0, G0), g1p = pk(G1, G1), g2p = pk(G2, G2);
    const u64 h0p = pk(H0, H0), h1p = pk(H1, H1), h2p = pk(H2, H2), h3p = pk(H3, H3);

    const int R = 2*OY0 - 3;               // window index m: input row = R + m, m = 0..37
    const int cofs = 4 + 2*c;              // float offset of this thread's window center-pair

    // ---- prologue: group A = rows m0..13, group B = rows m14..21 ----
    stage_rows(xin, srow, c, R, 0, 14); commit_group();
    stage_rows(xin, srow, c, R, 14, 8); commit_group();
    wait_group1();                         // A complete
    __syncthreads();

    u64 rxy[8], rzw[8];
    #pragma unroll
    for (int j = 0; j < 6; j++)            // ring fill: m=0..5 -> slots 0..5
        hfilt_row(&srow[j*ROWSTRIDE + cofs], g0p, g1p, g2p, h0p, h1p, h2p, h3p,
                  rxy[j], rzw[j]);

    #pragma unroll 1
    for (int i = 0; i < 4; ++i) {          // 4 output rows per iteration
        if (i > 0) {                       // retire group carrying rows m <= 8i+13
            wait_group1();
            __syncthreads();
        }
        if (i < 2) stage_rows(xin, srow, c, R, 22 + 8*i, 8);
        commit_group();                    // empty group for i>=2 keeps wait bookkeeping

        #pragma unroll
        for (int u = 0; u < 4; ++u) {
            const int m6 = 8*i + 6 + 2*u;  // two new rows completing window m..m+7
            hfilt_row(&srow[((m6    ) & (NSLOT-1))*ROWSTRIDE + cofs],
                      g0p, g1p, g2p, h0p, h1p, h2p, h3p,
                      rxy[(6 + 2*u) & 7], rzw[(6 + 2*u) & 7]);
            hfilt_row(&srow[((m6 + 1) & (NSLOT-1))*ROWSTRIDE + cofs],
                      g0p, g1p, g2p, h0p, h1p, h2p, h3p,
                      rxy[(7 + 2*u) & 7], rzw[(7 + 2*u) & 7]);

            const int w0 = 2*u;            // compile-time window base in the ring

            float llp, m15, m165, m45, m135, m75, m105;
            #pragma unroll
            for (int plane = 0; plane < 2; plane++) {
                const u64* r = plane ? rzw : rxy;
                const u64 r0 = r[(w0 + 0) & 7], r1 = r[(w0 + 1) & 7];
                const u64 r2 = r[(w0 + 2) & 7], r3 = r[(w0 + 3) & 7];
                const u64 r4 = r[(w0 + 4) & 7], r5 = r[(w0 + 5) & 7];
                const u64 r6 = r[(w0 + 6) & 7], r7 = r[(w0 + 7) & 7];

                const u64 A06 = add2(r0, r6), A15 = add2(r1, r5), A24 = add2(r2, r4);
                const u64 A17 = add2(r1, r7), A26 = add2(r2, r6), A35 = add2(r3, r5);

                const u64 F0 = fma2(A06, h0p, fma2(A15, h1p, fma2(A24, h2p, mul2(r3, h3p))));
                const u64 F1 = fma2(A17, h0p, fma2(A26, h1p, fma2(A35, h2p, mul2(r4, h3p))));
                const u64 E0 = fma2(A15, g0p, fma2(A24, g1p, mul2(r3, g2p)));
                const u64 E1 = fma2(A26, g0p, fma2(A35, g1p, mul2(r4, g2p)));

                float f0x, f0y, f1x, f1y;
                upk(F0, f0x, f0y); upk(F1, f1x, f1y);

                if (plane == 0) {
                    m15  = bandmag(f0x - f1y, f0y + f1x);
                    m165 = bandmag(f0x + f1y, f0y - f1x);
                    float s0, s1;
                    upk(add2(E0, E1), s0, s1);
                    llp = 0.25f * (s0 + s1);
                } else {
                    m45  = bandmag(f0x - f1y, f0y + f1x);
                    m135 = bandmag(f0x + f1y, f0y - f1x);
                    float e0x, e0y, e1x, e1y;
                    upk(E0, e0x, e0y); upk(E1, e1x, e1y);
                    m75  = bandmag(e0x - e1y, e0y + e1x);
                    m105 = bandmag(e0x + e1y, e0y - e1x);
                }
            }

            float* o = out + obase + (size_t)(4*i + u)*256;
            o[0]    = llp;
            o[1*cs] = m15;
            o[2*cs] = m45;
            o[3*cs] = m75;
            o[4*cs] = m105;
            o[5*cs] = m135;
            o[6*cs] = m165;
        }
    }
}

extern "C" void kernel_launch(void* const* d_in, const int* in_sizes, int n_in,
                              void* d_out, int out_size) {
    const float* x = (const float*)d_in[0];
    float* out = (float*)d_out;

    cudaFuncSetAttribute(scat_kernel,
                         cudaFuncAttributeMaxDynamicSharedMemorySize, SMEM_BYTES);

    dim3 grid(1, 256/TILE_OY, 96);         // (1, 16, 96)
    scat_kernel<<<grid, NTHREADS, SMEM_BYTES>>>(x, out);
}

// round 10
// speedup vs baseline: 3.4220x; 1.0264x over previous
#include <cuda_runtime.h>
#include <math.h>

// Fused DTCWT scattering layer, round 10: round 9 + 4 CTAs/SM occupancy push.
//  - 32-slot smem ring of PADDED rows (4+512+4) -> uniform branch-free hfilt
//  - 4 output rows per barrier; compile-time ring indices
//  - packed f32x2 filters with symmetric-tap sharing
//  - __launch_bounds__(256,4): 64-reg budget, 32 warps/SM
// x: (32,3,512,512) f32 -> out: (32,21,256,256) f32

#define TILE_OY 16
#define NTHREADS 256
#define ROWSTRIDE 524              // 4 pad | 512 data | 4 pad | 4 spare (floats)
#define NSLOT 32
#define SMEM_BYTES (NSLOT*ROWSTRIDE*4)   // 67072

// h0: [-0.05, 0.25, 0.6, 0.25, -0.05]  (symmetric)
#define G0 (-0.05f)
#define G1 (0.25f)
#define G2 (0.6f)
// h1: [-0.0107143, 0.0535714, 0.2607143, -0.6071429, ...] (symmetric)
#define H0 (-0.0107143f)
#define H1 (0.0535714f)
#define H2 (0.2607143f)
#define H3 (-0.6071429f)

typedef unsigned long long u64;

__device__ __forceinline__ u64 pk(float lo, float hi) {
    u64 r; asm("mov.b64 %0,{%1,%2};" : "=l"(r) : "f"(lo), "f"(hi)); return r;
}
__device__ __forceinline__ void upk(u64 v, float& a, float& b) {
    asm("mov.b64 {%0,%1},%2;" : "=f"(a), "=f"(b) : "l"(v));
}
__device__ __forceinline__ u64 add2(u64 a, u64 b) {
    u64 r; asm("add.rn.f32x2 %0,%1,%2;" : "=l"(r) : "l"(a), "l"(b)); return r;
}
__device__ __forceinline__ u64 mul2(u64 a, u64 b) {
    u64 r; asm("mul.rn.f32x2 %0,%1,%2;" : "=l"(r) : "l"(a), "l"(b)); return r;
}
__device__ __forceinline__ u64 fma2(u64 a, u64 b, u64 c) {
    u64 r; asm("fma.rn.f32x2 %0,%1,%2,%3;" : "=l"(r) : "l"(a), "l"(b), "l"(c)); return r;
}

__device__ __forceinline__ int refl(int i) {
    i = (i < 0) ? (-i - 1) : i;
    return (i > 511) ? (1023 - i) : i;
}
__device__ __forceinline__ float sqrt_approx(float v) {
    float r; asm("sqrt.approx.f32 %0, %1;" : "=f"(r) : "f"(v)); return r;
}
// band value = sqrt((re^2+im^2)/2 + 1e-4) - 0.01  (1/sqrt2 folded in)
__device__ __forceinline__ float bandmag(float re, float im) {
    return sqrt_approx(0.5f * fmaf(re, re, fmaf(im, im, 2e-4f))) - 0.01f;
}

__device__ __forceinline__ void commit_group() {
    asm volatile("cp.async.commit_group;\n" ::: "memory");
}
__device__ __forceinline__ void wait_group1() {
    asm volatile("cp.async.wait_group 1;\n" ::: "memory");
}

// stage nr rows starting at window-index m0 (nr even): nr/2 cp.async per thread,
// plus reflected pads (8 per row) filled straight from global by threads t < 8*nr.
__device__ __forceinline__ void stage_rows(const float* __restrict__ xin, float* srow,
                                           int t, int R, int m0, int nr) {
    const int rl = t >> 7, chunk = t & 127;
    #pragma unroll
    for (int j = 0; j < 7; ++j) {
        if (j >= nr/2) break;
        const int m  = m0 + 2*j + rl;
        const int gy = refl(R + m);
        const float* src = xin + (size_t)gy*512 + chunk*4;
        unsigned dst = (unsigned)__cvta_generic_to_shared(
            &srow[(m & (NSLOT-1))*ROWSTRIDE + 4 + chunk*4]);
        asm volatile("cp.async.cg.shared.global [%0], [%1], 16;\n" :: "r"(dst), "l"(src) : "memory");
    }
    if (t < 8*nr) {
        const int k = t >> 3, pp = t & 7;
        const int m  = m0 + k;
        const int gy = refl(R + m);
        float* rb = &srow[(m & (NSLOT-1))*ROWSTRIDE];
        if (pp < 4) rb[pp]       = __ldg(&xin[(size_t)gy*512 + (3 - pp)]);   // cols -4..-1
        else        rb[512 + pp] = __ldg(&xin[(size_t)gy*512 + (515 - pp)]); // cols 512..515
    }
}

// branch-free horizontal filters: p = row_base + 4 + 2c
__device__ __forceinline__ void hfilt_row(const float* __restrict__ p,
                                          u64 g0p, u64 g1p, u64 g2p,
                                          u64 h0p, u64 h1p, u64 h2p, u64 h3p,
                                          u64& loxy, u64& hizw) {
    const u64 PA = *(const u64*)(p - 4);   // (w-1,w0)
    const u64 PB = *(const u64*)(p - 2);   // (w1,w2)
    const u64 PC = *(const u64*)(p    );   // (w3,w4)
    const u64 PD = *(const u64*)(p + 2);   // (w5,w6)
    const u64 PE = *(const u64*)(p + 4);   // (w7,w8)
    float am, a0, b1, b2, c3, c4, d5, d6, e7, e8;
    upk(PA, am, a0); upk(PB, b1, b2); upk(PC, c3, c4);
    upk(PD, d5, d6); upk(PE, e7, e8);
    const u64 S1 = add2(PB, PD);                  // (w1+w5, w2+w6)
    const u64 S2 = pk(b2 + c4, c3 + d5);          // (w2+w4, w3+w5)
    const u64 T1 = pk(a0 + d6, b1 + e7);          // (w0+w6, w1+w7)
    loxy = fma2(S1, g0p, fma2(S2, g1p, mul2(PC, g2p)));
    hizw = fma2(T1, h0p, fma2(S1, h1p, fma2(S2, h2p, mul2(PC, h3p))));
}

__global__ __launch_bounds__(NTHREADS, 4) void scat_kernel(
    const float* __restrict__ x,
    float* __restrict__ out)
{
    extern __shared__ float srow[];        // [NSLOT][ROWSTRIDE]

    const int c   = threadIdx.x;           // pair-column 0..255
    const int img = blockIdx.z;
    const int OY0 = blockIdx.y * TILE_OY;
    const float* __restrict__ xin = x + (size_t)img * (512*512);

    const int b_  = img / 3;
    const int ch_ = img % 3;
    float* o = out + (((size_t)b_*21 + ch_)*256 + OY0)*256 + c;   // walked by +256/row
    const size_t cs = (size_t)3*256*256;

    const u64 g0p = pk(G0, G0), g1p = pk(G1, G1), g2p = pk(G2, G2);
    const u64 h0p = pk(H0, H0), h1p = pk(H1, H1), h2p = pk(H2, H2), h3p = pk(H3, H3);

    const int R = 2*OY0 - 3;               // input row = R + m, m = 0..37
    const int cofs = 4 + 2*c;

    // ---- prologue: group A = rows m0..13, group B = rows m14..21 ----
    stage_rows(xin, srow, c, R, 0, 14); commit_group();
    stage_rows(xin, srow, c, R, 14, 8); commit_group();
    wait_group1();                         // A complete
    __syncthreads();

    u64 rxy[8], rzw[8];
    #pragma unroll
    for (int j = 0; j < 6; j++)            // ring fill: m=0..5 -> slots 0..5
        hfilt_row(&srow[j*ROWSTRIDE + cofs], g0p, g1p, g2p, h0p, h1p, h2p, h3p,
                  rxy[j], rzw[j]);

    #pragma unroll 1
    for (int i = 0; i < 4; ++i) {          // 4 output rows per iteration
        if (i > 0) {
            wait_group1();
            __syncthreads();
        }
        if (i < 2) stage_rows(xin, srow, c, R, 22 + 8*i, 8);
        commit_group();                    // empty group for i>=2 keeps wait bookkeeping

        #pragma unroll
        for (int u = 0; u < 4; ++u) {
            const int m6 = 8*i + 6 + 2*u;
            hfilt_row(&srow[((m6    ) & (NSLOT-1))*ROWSTRIDE + cofs],
                      g0p, g1p, g2p, h0p, h1p, h2p, h3p,
                      rxy[(6 + 2*u) & 7], rzw[(6 + 2*u) & 7]);
            hfilt_row(&srow[((m6 + 1) & (NSLOT-1))*ROWSTRIDE + cofs],
                      g0p, g1p, g2p, h0p, h1p, h2p, h3p,
                      rxy[(7 + 2*u) & 7], rzw[(7 + 2*u) & 7]);

            const int w0 = 2*u;            // compile-time window base

            float llp, m15, m165, m45, m135, m75, m105;
            #pragma unroll
            for (int plane = 0; plane < 2; plane++) {
                const u64* r = plane ? rzw : rxy;
                const u64 r0 = r[(w0 + 0) & 7], r1 = r[(w0 + 1) & 7];
                const u64 r2 = r[(w0 + 2) & 7], r3 = r[(w0 + 3) & 7];
                const u64 r4 = r[(w0 + 4) & 7], r5 = r[(w0 + 5) & 7];
                const u64 r6 = r[(w0 + 6) & 7], r7 = r[(w0 + 7) & 7];

                const u64 A06 = add2(r0, r6), A15 = add2(r1, r5), A24 = add2(r2, r4);
                const u64 A17 = add2(r1, r7), A26 = add2(r2, r6), A35 = add2(r3, r5);

                const u64 F0 = fma2(A06, h0p, fma2(A15, h1p, fma2(A24, h2p, mul2(r3, h3p))));
                const u64 F1 = fma2(A17, h0p, fma2(A26, h1p, fma2(A35, h2p, mul2(r4, h3p))));
                const u64 E0 = fma2(A15, g0p, fma2(A24, g1p, mul2(r3, g2p)));
                const u64 E1 = fma2(A26, g0p, fma2(A35, g1p, mul2(r4, g2p)));

                float f0x, f0y, f1x, f1y;
                upk(F0, f0x, f0y); upk(F1, f1x, f1y);

                if (plane == 0) {
                    m15  = bandmag(f0x - f1y, f0y + f1x);
                    m165 = bandmag(f0x + f1y, f0y - f1x);
                    float s0, s1;
                    upk(add2(E0, E1), s0, s1);
                    llp = 0.25f * (s0 + s1);
                } else {
                    m45  = bandmag(f0x - f1y, f0y + f1x);
                    m135 = bandmag(f0x + f1y, f0y - f1x);
                    float e0x, e0y, e1x, e1y;
                    upk(E0, e0x, e0y); upk(E1, e1x, e1y);
                    m75  = bandmag(e0x - e1y, e0y + e1x);
                    m105 = bandmag(e0x + e1y, e0y - e1x);
                }
            }

            o[0]    = llp;
            o[1*cs] = m15;
            o[2*cs] = m45;
            o[3*cs] = m75;
            o[4*cs] = m105;
            o[5*cs] = m135;
            o[6*cs] = m165;
            o += 256;                      // next output row
        }
    }
}

extern "C" void kernel_launch(void* const* d_in, const int* in_sizes, int n_in,
                              void* d_out, int out_size) {
    const float* x = (const float*)d_in[0];
    float* out = (float*)d_out;

    cudaFuncSetAttribute(scat_kernel,
                         cudaFuncAttributeMaxDynamicSharedMemorySize, SMEM_BYTES);

    dim3 grid(1, 256/TILE_OY, 96);         // (1, 16, 96)
    scat_kernel<<<grid, NTHREADS, SMEM_BYTES>>>(x, out);
}

// round 11
// speedup vs baseline: 3.5451x; 1.0360x over previous
#include <cuda_runtime.h>
#include <math.h>

// Fused DTCWT scattering layer, round 11: 16-slot ring -> 4 CTAs/SM (smem was the occ limiter).
//  - 16-slot smem ring of PADDED rows (4+512+4), distance-1 prefetch, wait_group 0
//  - 4 output rows per barrier; compile-time ring indices
//  - packed f32x2 filters with symmetric-tap sharing; 64-reg budget
// x: (32,3,512,512) f32 -> out: (32,21,256,256) f32

#define TILE_OY 16
#define NTHREADS 256
#define ROWSTRIDE 524              // 4 pad | 512 data | 4 pad | 4 spare (floats)
#define NSLOT 16
#define SMEM_BYTES (NSLOT*ROWSTRIDE*4)   // 33536

// h0: [-0.05, 0.25, 0.6, 0.25, -0.05]  (symmetric)
#define G0 (-0.05f)
#define G1 (0.25f)
#define G2 (0.6f)
// h1: [-0.0107143, 0.0535714, 0.2607143, -0.6071429, ...] (symmetric)
#define H0 (-0.0107143f)
#define H1 (0.0535714f)
#define H2 (0.2607143f)
#define H3 (-0.6071429f)

typedef unsigned long long u64;

__device__ __forceinline__ u64 pk(float lo, float hi) {
    u64 r; asm("mov.b64 %0,{%1,%2};" : "=l"(r) : "f"(lo), "f"(hi)); return r;
}
__device__ __forceinline__ void upk(u64 v, float& a, float& b) {
    asm("mov.b64 {%0,%1},%2;" : "=f"(a), "=f"(b) : "l"(v));
}
__device__ __forceinline__ u64 add2(u64 a, u64 b) {
    u64 r; asm("add.rn.f32x2 %0,%1,%2;" : "=l"(r) : "l"(a), "l"(b)); return r;
}
__device__ __forceinline__ u64 mul2(u64 a, u64 b) {
    u64 r; asm("mul.rn.f32x2 %0,%1,%2;" : "=l"(r) : "l"(a), "l"(b)); return r;
}
__device__ __forceinline__ u64 fma2(u64 a, u64 b, u64 c) {
    u64 r; asm("fma.rn.f32x2 %0,%1,%2,%3;" : "=l"(r) : "l"(a), "l"(b), "l"(c)); return r;
}

__device__ __forceinline__ int refl(int i) {
    i = (i < 0) ? (-i - 1) : i;
    return (i > 511) ? (1023 - i) : i;
}
__device__ __forceinline__ float sqrt_approx(float v) {
    float r; asm("sqrt.approx.f32 %0, %1;" : "=f"(r) : "f"(v)); return r;
}
// band value = sqrt((re^2+im^2)/2 + 1e-4) - 0.01  (1/sqrt2 folded in)
__device__ __forceinline__ float bandmag(float re, float im) {
    return sqrt_approx(0.5f * fmaf(re, re, fmaf(im, im, 2e-4f))) - 0.01f;
}

__device__ __forceinline__ void commit_group() {
    asm volatile("cp.async.commit_group;\n" ::: "memory");
}
__device__ __forceinline__ void wait_all() {
    asm volatile("cp.async.wait_group 0;\n" ::: "memory");
}

// stage nr rows starting at window-index m0 (nr even): nr/2 cp.async per thread,
// plus reflected pads (8 per row) filled straight from global by threads t < 8*nr.
__device__ __forceinline__ void stage_rows(const float* __restrict__ xin, float* srow,
                                           int t, int R, int m0, int nr) {
    const int rl = t >> 7, chunk = t & 127;
    #pragma unroll
    for (int j = 0; j < 7; ++j) {
        if (j >= nr/2) break;
        const int m  = m0 + 2*j + rl;
        const int gy = refl(R + m);
        const float* src = xin + (size_t)gy*512 + chunk*4;
        unsigned dst = (unsigned)__cvta_generic_to_shared(
            &srow[(m & (NSLOT-1))*ROWSTRIDE + 4 + chunk*4]);
        asm volatile("cp.async.cg.shared.global [%0], [%1], 16;\n" :: "r"(dst), "l"(src) : "memory");
    }
    if (t < 8*nr) {
        const int k = t >> 3, pp = t & 7;
        const int m  = m0 + k;
        const int gy = refl(R + m);
        float* rb = &srow[(m & (NSLOT-1))*ROWSTRIDE];
        if (pp < 4) rb[pp]       = __ldg(&xin[(size_t)gy*512 + (3 - pp)]);   // cols -4..-1
        else        rb[512 + pp] = __ldg(&xin[(size_t)gy*512 + (515 - pp)]); // cols 512..515
    }
}

// branch-free horizontal filters: p = row_base + 4 + 2c
__device__ __forceinline__ void hfilt_row(const float* __restrict__ p,
                                          u64 g0p, u64 g1p, u64 g2p,
                                          u64 h0p, u64 h1p, u64 h2p, u64 h3p,
                                          u64& loxy, u64& hizw) {
    const u64 PA = *(const u64*)(p - 4);   // (w-1,w0)
    const u64 PB = *(const u64*)(p - 2);   // (w1,w2)
    const u64 PC = *(const u64*)(p    );   // (w3,w4)
    const u64 PD = *(const u64*)(p + 2);   // (w5,w6)
    const u64 PE = *(const u64*)(p + 4);   // (w7,w8)
    float am, a0, b1, b2, c3, c4, d5, d6, e7, e8;
    upk(PA, am, a0); upk(PB, b1, b2); upk(PC, c3, c4);
    upk(PD, d5, d6); upk(PE, e7, e8);
    const u64 S1 = add2(PB, PD);                  // (w1+w5, w2+w6)
    const u64 S2 = pk(b2 + c4, c3 + d5);          // (w2+w4, w3+w5)
    const u64 T1 = pk(a0 + d6, b1 + e7);          // (w0+w6, w1+w7)
    loxy = fma2(S1, g0p, fma2(S2, g1p, mul2(PC, g2p)));
    hizw = fma2(T1, h0p, fma2(S1, h1p, fma2(S2, h2p, mul2(PC, h3p))));
}

__global__ __launch_bounds__(NTHREADS, 4) void scat_kernel(
    const float* __restrict__ x,
    float* __restrict__ out)
{
    extern __shared__ float srow[];        // [NSLOT][ROWSTRIDE]

    const int c   = threadIdx.x;           // pair-column 0..255
    const int img = blockIdx.z;
    const int OY0 = blockIdx.y * TILE_OY;
    const float* __restrict__ xin = x + (size_t)img * (512*512);

    const int b_  = img / 3;
    const int ch_ = img % 3;
    float* o = out + (((size_t)b_*21 + ch_)*256 + OY0)*256 + c;   // walked by +256/row
    const size_t cs = (size_t)3*256*256;

    const u64 g0p = pk(G0, G0), g1p = pk(G1, G1), g2p = pk(G2, G2);
    const u64 h0p = pk(H0, H0), h1p = pk(H1, H1), h2p = pk(H2, H2), h3p = pk(H3, H3);

    const int R = 2*OY0 - 3;               // input row = R + m, m = 0..37
    const int cofs = 4 + 2*c;

    // ---- prologue: stage rows m=0..13, ring-fill m=0..5 ----
    stage_rows(xin, srow, c, R, 0, 14); commit_group();
    wait_all();
    __syncthreads();

    u64 rxy[8], rzw[8];
    #pragma unroll
    for (int j = 0; j < 6; j++)
        hfilt_row(&srow[j*ROWSTRIDE + cofs], g0p, g1p, g2p, h0p, h1p, h2p, h3p,
                  rxy[j], rzw[j]);
    __syncthreads();                       // slots 0..5 free for iter-0 staging (rows 16..21)

    #pragma unroll 1
    for (int i = 0; i < 4; ++i) {          // 4 output rows per iteration
        if (i > 0) {                       // rows 6+8i..13+8i (staged at iter i-1) landed
            wait_all();
            __syncthreads();
        }
        if (i < 3) {                       // stage rows for iter i+1
            stage_rows(xin, srow, c, R, 14 + 8*i, 8);
            commit_group();
        }

        #pragma unroll
        for (int u = 0; u < 4; ++u) {
            const int m6 = 8*i + 6 + 2*u;  // two new rows completing window m..m+7
            hfilt_row(&srow[((m6    ) & (NSLOT-1))*ROWSTRIDE + cofs],
                      g0p, g1p, g2p, h0p, h1p, h2p, h3p,
                      rxy[(6 + 2*u) & 7], rzw[(6 + 2*u) & 7]);
            hfilt_row(&srow[((m6 + 1) & (NSLOT-1))*ROWSTRIDE + cofs],
                      g0p, g1p, g2p, h0p, h1p, h2p, h3p,
                      rxy[(7 + 2*u) & 7], rzw[(7 + 2*u) & 7]);

            const int w0 = 2*u;            // compile-time window base

            float llp, m15, m165, m45, m135, m75, m105;
            #pragma unroll
            for (int plane = 0; plane < 2; plane++) {
                const u64* r = plane ? rzw : rxy;
                const u64 r0 = r[(w0 + 0) & 7], r1 = r[(w0 + 1) & 7];
                const u64 r2 = r[(w0 + 2) & 7], r3 = r[(w0 + 3) & 7];
                const u64 r4 = r[(w0 + 4) & 7], r5 = r[(w0 + 5) & 7];
                const u64 r6 = r[(w0 + 6) & 7], r7 = r[(w0 + 7) & 7];

                const u64 A06 = add2(r0, r6), A15 = add2(r1, r5), A24 = add2(r2, r4);
                const u64 A17 = add2(r1, r7), A26 = add2(r2, r6), A35 = add2(r3, r5);

                const u64 F0 = fma2(A06, h0p, fma2(A15, h1p, fma2(A24, h2p, mul2(r3, h3p))));
                const u64 F1 = fma2(A17, h0p, fma2(A26, h1p, fma2(A35, h2p, mul2(r4, h3p))));
                const u64 E0 = fma2(A15, g0p, fma2(A24, g1p, mul2(r3, g2p)));
                const u64 E1 = fma2(A26, g0p, fma2(A35, g1p, mul2(r4, g2p)));

                float f0x, f0y, f1x, f1y;
                upk(F0, f0x, f0y); upk(F1, f1x, f1y);

                if (plane == 0) {
                    m15  = bandmag(f0x - f1y, f0y + f1x);
                    m165 = bandmag(f0x + f1y, f0y - f1x);
                    float s0, s1;
                    upk(add2(E0, E1), s0, s1);
                    llp = 0.25f * (s0 + s1);
                } else {
                    m45  = bandmag(f0x - f1y, f0y + f1x);
                    m135 = bandmag(f0x + f1y, f0y - f1x);
                    float e0x, e0y, e1x, e1y;
                    upk(E0, e0x, e0y); upk(E1, e1x, e1y);
                    m75  = bandmag(e0x - e1y, e0y + e1x);
                    m105 = bandmag(e0x + e1y, e0y - e1x);
                }
            }

            o[0]    = llp;
            o[1*cs] = m15;
            o[2*cs] = m45;
            o[3*cs] = m75;
            o[4*cs] = m105;
            o[5*cs] = m135;
            o[6*cs] = m165;
            o += 256;                      // next output row
        }
    }
}

extern "C" void kernel_launch(void* const* d_in, const int* in_sizes, int n_in,
                              void* d_out, int out_size) {
    const float* x = (const float*)d_in[0];
    float* out = (float*)d_out;

    cudaFuncSetAttribute(scat_kernel,
                         cudaFuncAttributeMaxDynamicSharedMemorySize, SMEM_BYTES);

    dim3 grid(1, 256/TILE_OY, 96);         // (1, 16, 96)
    scat_kernel<<<grid, NTHREADS, SMEM_BYTES>>>(x, out);
}

// round 12
// speedup vs baseline: 3.6970x; 1.0429x over previous
#include <cuda_runtime.h>
#include <math.h>

// Fused DTCWT scattering layer, round 12: round 11 + fully-async pad staging.
//  - 16-slot smem ring of PADDED rows (4+512+4); pads now via cp.async 4B (no LDG stragglers)
//  - 4 output rows per barrier; compile-time ring indices; distance-1 prefetch
//  - packed f32x2 filters with symmetric-tap sharing; direct pooled-LL filter
// x: (32,3,512,512) f32 -> out: (32,21,256,256) f32

#define TILE_OY 16
#define NTHREADS 256
#define ROWSTRIDE 524              // 4 pad | 512 data | 4 pad | 4 spare (floats)
#define NSLOT 16
#define SMEM_BYTES (NSLOT*ROWSTRIDE*4)   // 33536

// h0: [-0.05, 0.25, 0.6, 0.25, -0.05]  (symmetric)
#define G0 (-0.05f)
#define G1 (0.25f)
#define G2 (0.6f)
// h1: [-0.0107143, 0.0535714, 0.2607143, -0.6071429, ...] (symmetric)
#define H0 (-0.0107143f)
#define H1 (0.0535714f)
#define H2 (0.2607143f)
#define H3 (-0.6071429f)

typedef unsigned long long u64;

__device__ __forceinline__ u64 pk(float lo, float hi) {
    u64 r; asm("mov.b64 %0,{%1,%2};" : "=l"(r) : "f"(lo), "f"(hi)); return r;
}
__device__ __forceinline__ void upk(u64 v, float& a, float& b) {
    asm("mov.b64 {%0,%1},%2;" : "=f"(a), "=f"(b) : "l"(v));
}
__device__ __forceinline__ u64 add2(u64 a, u64 b) {
    u64 r; asm("add.rn.f32x2 %0,%1,%2;" : "=l"(r) : "l"(a), "l"(b)); return r;
}
__device__ __forceinline__ u64 mul2(u64 a, u64 b) {
    u64 r; asm("mul.rn.f32x2 %0,%1,%2;" : "=l"(r) : "l"(a), "l"(b)); return r;
}
__device__ __forceinline__ u64 fma2(u64 a, u64 b, u64 c) {
    u64 r; asm("fma.rn.f32x2 %0,%1,%2,%3;" : "=l"(r) : "l"(a), "l"(b), "l"(c)); return r;
}

__device__ __forceinline__ int refl(int i) {
    i = (i < 0) ? (-i - 1) : i;
    return (i > 511) ? (1023 - i) : i;
}
__device__ __forceinline__ float sqrt_approx(float v) {
    float r; asm("sqrt.approx.f32 %0, %1;" : "=f"(r) : "f"(v)); return r;
}
// band value = sqrt((re^2+im^2)/2 + 1e-4) - 0.01  (1/sqrt2 folded in)
__device__ __forceinline__ float bandmag(float re, float im) {
    return sqrt_approx(0.5f * fmaf(re, re, fmaf(im, im, 2e-4f))) - 0.01f;
}

__device__ __forceinline__ void commit_group() {
    asm volatile("cp.async.commit_group;\n" ::: "memory");
}
__device__ __forceinline__ void wait_all() {
    asm volatile("cp.async.wait_group 0;\n" ::: "memory");
}

// stage nr rows starting at window-index m0 (nr even, nr<=14):
//  - row bodies: nr/2 x 16B cp.async.cg per thread
//  - reflected pads (8 per row): one 4B cp.async.ca per thread (t < 8*nr) -- fully async,
//    same commit group, so no synchronous-LDG barrier stragglers.
__device__ __forceinline__ void stage_rows(const float* __restrict__ xin, float* srow,
                                           int t, int R, int m0, int nr) {
    const int rl = t >> 7, chunk = t & 127;
    #pragma unroll
    for (int j = 0; j < 7; ++j) {
        if (j >= nr/2) break;
        const int m  = m0 + 2*j + rl;
        const int gy = refl(R + m);
        const float* src = xin + (size_t)gy*512 + chunk*4;
        unsigned dst = (unsigned)__cvta_generic_to_shared(
            &srow[(m & (NSLOT-1))*ROWSTRIDE + 4 + chunk*4]);
        asm volatile("cp.async.cg.shared.global [%0], [%1], 16;\n" :: "r"(dst), "l"(src) : "memory");
    }
    if (t < 8*nr) {
        const int k = t >> 3, pp = t & 7;
        const int m  = m0 + k;
        const int gy = refl(R + m);
        const int srccol = (pp < 4) ? (3 - pp) : (515 - pp);   // reflected source col
        const int dstofs = (pp < 4) ? pp : (512 + pp);
        const float* src = xin + (size_t)gy*512 + srccol;
        unsigned dst = (unsigned)__cvta_generic_to_shared(
            &srow[(m & (NSLOT-1))*ROWSTRIDE + dstofs]);
        asm volatile("cp.async.ca.shared.global [%0], [%1], 4;\n" :: "r"(dst), "l"(src) : "memory");
    }
}

// branch-free horizontal filters: p = row_base + 4 + 2c
__device__ __forceinline__ void hfilt_row(const float* __restrict__ p,
                                          u64 g0p, u64 g1p, u64 g2p,
                                          u64 h0p, u64 h1p, u64 h2p, u64 h3p,
                                          u64& loxy, u64& hizw) {
    const u64 PA = *(const u64*)(p - 4);   // (w-1,w0)
    const u64 PB = *(const u64*)(p - 2);   // (w1,w2)
    const u64 PC = *(const u64*)(p    );   // (w3,w4)
    const u64 PD = *(const u64*)(p + 2);   // (w5,w6)
    const u64 PE = *(const u64*)(p + 4);   // (w7,w8)
    float am, a0, b1, b2, c3, c4, d5, d6, e7, e8;
    upk(PA, am, a0); upk(PB, b1, b2); upk(PC, c3, c4);
    upk(PD, d5, d6); upk(PE, e7, e8);
    const u64 S1 = add2(PB, PD);                  // (w1+w5, w2+w6)
    const u64 S2 = pk(b2 + c4, c3 + d5);          // (w2+w4, w3+w5)
    const u64 T1 = pk(a0 + d6, b1 + e7);          // (w0+w6, w1+w7)
    loxy = fma2(S1, g0p, fma2(S2, g1p, mul2(PC, g2p)));
    hizw = fma2(T1, h0p, fma2(S1, h1p, fma2(S2, h2p, mul2(PC, h3p))));
}

__global__ __launch_bounds__(NTHREADS, 4) void scat_kernel(
    const float* __restrict__ x,
    float* __restrict__ out)
{
    extern __shared__ float srow[];        // [NSLOT][ROWSTRIDE]

    const int c   = threadIdx.x;           // pair-column 0..255
    const int img = blockIdx.z;
    const int OY0 = blockIdx.y * TILE_OY;
    const float* __restrict__ xin = x + (size_t)img * (512*512);

    const int b_  = img / 3;
    const int ch_ = img % 3;
    float* o = out + (((size_t)b_*21 + ch_)*256 + OY0)*256 + c;   // walked by +256/row
    const size_t cs = (size_t)3*256*256;

    const u64 g0p = pk(G0, G0), g1p = pk(G1, G1), g2p = pk(G2, G2);
    const u64 h0p = pk(H0, H0), h1p = pk(H1, H1), h2p = pk(H2, H2), h3p = pk(H3, H3);

    const int R = 2*OY0 - 3;               // input row = R + m, m = 0..37
    const int cofs = 4 + 2*c;

    // ---- prologue: stage rows m=0..13, ring-fill m=0..5 ----
    stage_rows(xin, srow, c, R, 0, 14); commit_group();
    wait_all();
    __syncthreads();

    u64 rxy[8], rzw[8];
    #pragma unroll
    for (int j = 0; j < 6; j++)
        hfilt_row(&srow[j*ROWSTRIDE + cofs], g0p, g1p, g2p, h0p, h1p, h2p, h3p,
                  rxy[j], rzw[j]);
    __syncthreads();                       // slots 0..5 free for iter-0 staging

    #pragma unroll 1
    for (int i = 0; i < 4; ++i) {          // 4 output rows per iteration
        if (i > 0) {                       // rows 6+8i..13+8i landed
            wait_all();
            __syncthreads();
        }
        if (i < 3) {                       // stage rows for iter i+1
            stage_rows(xin, srow, c, R, 14 + 8*i, 8);
            commit_group();
        }

        #pragma unroll
        for (int u = 0; u < 4; ++u) {
            const int m6 = 8*i + 6 + 2*u;  // two new rows completing window m..m+7
            hfilt_row(&srow[((m6    ) & (NSLOT-1))*ROWSTRIDE + cofs],
                      g0p, g1p, g2p, h0p, h1p, h2p, h3p,
                      rxy[(6 + 2*u) & 7], rzw[(6 + 2*u) & 7]);
            hfilt_row(&srow[((m6 + 1) & (NSLOT-1))*ROWSTRIDE + cofs],
                      g0p, g1p, g2p, h0p, h1p, h2p, h3p,
                      rxy[(7 + 2*u) & 7], rzw[(7 + 2*u) & 7]);

            const int w0 = 2*u;            // compile-time window base

            float llp, m15, m165, m45, m135, m75, m105;
            #pragma unroll
            for (int plane = 0; plane < 2; plane++) {
                const u64* r = plane ? rzw : rxy;
                const u64 r0 = r[(w0 + 0) & 7], r1 = r[(w0 + 1) & 7];
                const u64 r2 = r[(w0 + 2) & 7], r3 = r[(w0 + 3) & 7];
                const u64 r4 = r[(w0 + 4) & 7], r5 = r[(w0 + 5) & 7];
                const u64 r6 = r[(w0 + 6) & 7], r7 = r[(w0 + 7) & 7];

                const u64 A06 = add2(r0, r6), A15 = add2(r1, r5), A24 = add2(r2, r4);
                const u64 A17 = add2(r1, r7), A26 = add2(r2, r6), A35 = add2(r3, r5);

                const u64 F0 = fma2(A06, h0p, fma2(A15, h1p, fma2(A24, h2p, mul2(r3, h3p))));
                const u64 F1 = fma2(A17, h0p, fma2(A26, h1p, fma2(A35, h2p, mul2(r4, h3p))));

                float f0x, f0y, f1x, f1y;
                upk(F0, f0x, f0y); upk(F1, f1x, f1y);

                if (plane == 0) {
                    m15  = bandmag(f0x - f1y, f0y + f1x);
                    m165 = bandmag(f0x + f1y, f0y - f1x);
                    // pooled LL: summed 5-tap filter applied once
                    const u64 B  = add2(A15, A26);
                    const u64 Cs = add2(A24, A35);
                    const u64 Ds = add2(r3, r4);
                    const u64 LLs = fma2(B, g0p, fma2(Cs, g1p, mul2(Ds, g2p)));
                    float s0, s1;
                    upk(LLs, s0, s1);
                    llp = 0.25f * (s0 + s1);
                } else {
                    m45  = bandmag(f0x - f1y, f0y + f1x);
                    m135 = bandmag(f0x + f1y, f0y - f1x);
                    const u64 E0 = fma2(A15, g0p, fma2(A24, g1p, mul2(r3, g2p)));
                    const u64 E1 = fma2(A26, g0p, fma2(A35, g1p, mul2(r4, g2p)));
                    float e0x, e0y, e1x, e1y;
                    upk(E0, e0x, e0y); upk(E1, e1x, e1y);
                    m75  = bandmag(e0x - e1y, e0y + e1x);
                    m105 = bandmag(e0x + e1y, e0y - e1x);
                }
            }

            o[0]    = llp;
            o[1*cs] = m15;
            o[2*cs] = m45;
            o[3*cs] = m75;
            o[4*cs] = m105;
            o[5*cs] = m135;
            o[6*cs] = m165;
            o += 256;                      // next output row
        }
    }
}

extern "C" void kernel_launch(void* const* d_in, const int* in_sizes, int n_in,
                              void* d_out, int out_size) {
    const float* x = (const float*)d_in[0];
    float* out = (float*)d_out;

    cudaFuncSetAttribute(scat_kernel,
                         cudaFuncAttributeMaxDynamicSharedMemorySize, SMEM_BYTES);

    dim3 grid(1, 256/TILE_OY, 96);         // (1, 16, 96)
    scat_kernel<<<grid, NTHREADS, SMEM_BYTES>>>(x, out);
}